// round 7
// baseline (speedup 1.0000x reference)
#include <cuda_runtime.h>
#include <cuda_bf16.h>
#include <cstdint>
#include <math.h>

#define SS    128
#define LFREQ 10

__device__ float g_dt;
__device__ __align__(16) unsigned char g_wbuf[40960];   // pre-swizzled bf16 hi/lo weights

#define GW_W1H 0
#define GW_W1L 8192
#define GW_W2H 16384
#define GW_W2L 24576
#define GW_WOH 32768
#define GW_WOL 36864

// ---------------- helpers ----------------
__device__ __forceinline__ uint32_t smem_to_u32(const void* p) {
    uint32_t a;
    asm("{ .reg .u64 t; cvta.to.shared.u64 t, %1; cvt.u32.u64 %0, t; }" : "=r"(a) : "l"(p));
    return a;
}

__device__ __forceinline__ void ldsm4(uint32_t* r, uint32_t addr) {
    asm volatile("ldmatrix.sync.aligned.m8n8.x4.shared.b16 {%0,%1,%2,%3}, [%4];"
        : "=r"(r[0]), "=r"(r[1]), "=r"(r[2]), "=r"(r[3]) : "r"(addr));
}

__device__ __forceinline__ void mma16816(float* d, const uint32_t* a, uint32_t b0, uint32_t b1) {
    asm volatile("mma.sync.aligned.m16n8k16.row.col.f32.bf16.bf16.f32 "
        "{%0,%1,%2,%3}, {%4,%5,%6,%7}, {%8,%9}, {%0,%1,%2,%3};"
        : "+f"(d[0]), "+f"(d[1]), "+f"(d[2]), "+f"(d[3])
        : "r"(a[0]), "r"(a[1]), "r"(a[2]), "r"(a[3]), "r"(b0), "r"(b1));
}

__device__ __forceinline__ void split1(float x, uint16_t& h, uint16_t& l) {
    uint16_t hb = __bfloat16_as_ushort(__float2bfloat16_rn(x));
    float r = __uint_as_float(((uint32_t)hb) << 16);
    uint16_t lb = __bfloat16_as_ushort(__float2bfloat16_rn(x - r));
    h = hb; l = lb;
}
__device__ __forceinline__ void split2(float a, float b, uint32_t& h, uint32_t& l) {
    uint16_t ha, la, hb2, lb2;
    split1(a, ha, la); split1(b, hb2, lb2);
    h = (uint32_t)ha | ((uint32_t)hb2 << 16);
    l = (uint32_t)la | ((uint32_t)lb2 << 16);
}

// swizzled tile byte offset: row-major, 128B rows, 16B granules XORed
__device__ __forceinline__ uint32_t sw_off(int row, int c4) {
    return (uint32_t)(row * 128 + ((c4 ^ (row & 7)) << 4));
}

// ---------------- SMEM layout (byte offsets) ----------------
#define SM_B1    0
#define SM_B2    256
#define SM_BO    512
#define SM_WRGB  640
#define SM_BRGB  832
#define SM_W     1024
#define SM_W1H   (SM_W + GW_W1H)
#define SM_W1L   (SM_W + GW_W1L)
#define SM_W2H   (SM_W + GW_W2H)
#define SM_W2L   (SM_W + GW_W2L)
#define SM_WOH   (SM_W + GW_WOH)
#define SM_WOL   (SM_W + GW_WOL)
#define SM_A     41984   // 2 rays x (16384 hi + 16384 lo)
#define SM_TOTAL (41984 + 65536)

#define TPB 256
#define RAYS_PER_CTA 2
#define NSM 148
#define NCTA (2 * NSM)

// -------- prep: dt reduction + weight conversion (one CTA) --------
__global__ void prep_kernel(const float* __restrict__ tmin, const float* __restrict__ tmax,
                            const float* __restrict__ W1, const float* __restrict__ W2,
                            const float* __restrict__ Wo, int n) {
    __shared__ float red[256];
    int tid = threadIdx.x;
    float acc = 0.f;
    for (int i = tid; i < n; i += 256) acc += tmax[i] - tmin[i];
    red[tid] = acc;
    __syncthreads();
    for (int s = 128; s > 0; s >>= 1) {
        if (tid < s) red[tid] += red[tid + s];
        __syncthreads();
    }
    if (tid == 0) g_dt = (red[0] / (float)n) / (float)SS;

    for (int idx = tid; idx < 64 * 64; idx += 256) {
        int nn = idx >> 6, k = idx & 63;
        float w = (k < 63) ? W1[k * 64 + nn] : 0.f;
        uint16_t h, l; split1(w, h, l);
        uint32_t off = sw_off(nn, k >> 3) + (k & 7) * 2;
        *(uint16_t*)(g_wbuf + GW_W1H + off) = h;
        *(uint16_t*)(g_wbuf + GW_W1L + off) = l;
    }
    for (int idx = tid; idx < 64 * 64; idx += 256) {
        int nn = idx >> 6, k = idx & 63;
        float w = W2[k * 64 + nn];
        uint16_t h, l; split1(w, h, l);
        uint32_t off = sw_off(nn, k >> 3) + (k & 7) * 2;
        *(uint16_t*)(g_wbuf + GW_W2H + off) = h;
        *(uint16_t*)(g_wbuf + GW_W2L + off) = l;
    }
    for (int idx = tid; idx < 32 * 64; idx += 256) {
        int nn = idx >> 6, k = idx & 63;
        float w = (nn < 17) ? Wo[k * 17 + nn] : 0.f;
        uint16_t h, l; split1(w, h, l);
        uint32_t off = sw_off(nn, k >> 3) + (k & 7) * 2;
        *(uint16_t*)(g_wbuf + GW_WOH + off) = h;
        *(uint16_t*)(g_wbuf + GW_WOL + off) = l;
    }
}

__global__ void __launch_bounds__(TPB, 2)
nerf_mma_kernel(const float* __restrict__ ox, const float* __restrict__ oy,
                const float* __restrict__ oz, const float* __restrict__ dxv,
                const float* __restrict__ dyv, const float* __restrict__ dzv,
                const float* __restrict__ tmin, const float* __restrict__ tmax,
                const float* __restrict__ b1, const float* __restrict__ b2,
                const float* __restrict__ bo,
                const float* __restrict__ Wrgb, const float* __restrict__ brgb,
                float* __restrict__ out, int n)
{
    extern __shared__ __align__(1024) char smem[];
    const uint32_t sb = smem_to_u32(smem);
    const int tid  = threadIdx.x;
    const int rayi = tid >> 7;
    const int rtid = tid & 127;
    const int lid  = tid & 31;
    const int wray = (tid >> 5) & 3;
    const int wbase = wray * 32;
    const uint32_t AH = SM_A + rayi * 32768;
    const uint32_t AL = AH + 16384;

    // ---- stage weights ONCE (persistent CTA) ----
    {
        const uint4* src = (const uint4*)g_wbuf;
        uint4* dst = (uint4*)(smem + SM_W);
        for (int i = tid; i < 2560; i += TPB) dst[i] = src[i];
        float* s = (float*)smem;
        for (int i = tid; i < 64; i += TPB) s[(SM_B1 >> 2) + i] = b1[i];
        for (int i = tid; i < 64; i += TPB) s[(SM_B2 >> 2) + i] = b2[i];
        for (int i = tid; i < 17; i += TPB) s[(SM_BO >> 2) + i] = bo[i];
        for (int i = tid; i < 48; i += TPB) s[(SM_WRGB >> 2) + i] = Wrgb[i];
        for (int i = tid; i < 3;  i += TPB) s[(SM_BRGB >> 2) + i] = brgb[i];
    }
    __syncthreads();

    // lane-derived ldmatrix coordinates
    const int lj = lid >> 3, lr = lid & 7;
    const int a_rl  = ((lj & 1) << 3) + lr;
    const int a_c4h = lj >> 1;
    const int b_nl  = ((lj >> 1) << 3) + lr;
    const int b_c4h = lj & 1;
    const int c2l   = 2 * (lid & 3);

    const int npairs = n / RAYS_PER_CTA;
    const float dtv = g_dt;

    for (int pair = blockIdx.x; pair < npairs; pair += gridDim.x) {

    // ---- positional encodings -> A tile (row = sample = rtid) ----
    const int ray = pair * RAYS_PER_CTA + rayi;
    const float tmn = tmin[ray], tmx = tmax[ray];
    const float t  = fmaf((float)rtid * (1.0f / (float)(SS - 1)), tmx - tmn, tmn);
    {
        float e[64];
        e[0] = fmaf(dxv[ray], t, ox[ray]);
        e[1] = fmaf(dyv[ray], t, oy[ray]);
        e[2] = fmaf(dzv[ray], t, oz[ray]);
        e[63] = 0.f;
#pragma unroll 1
        for (int c = 0; c < 3; c++) {
            float sv, cv;
            sincosf(e[c], &sv, &cv);
#pragma unroll
            for (int f = 0; f < LFREQ; f++) {
                e[3 + 20 * c + f]      = sv;
                e[3 + 20 * c + 10 + f] = cv;
                float ns = 2.0f * sv * cv;
                float nc = fmaf(cv, cv, -(sv * sv));
                sv = ns; cv = nc;
            }
        }
        uint32_t hi[32], lo[32];
#pragma unroll
        for (int j = 0; j < 32; j++) split2(e[2 * j], e[2 * j + 1], hi[j], lo[j]);
#pragma unroll
        for (int q = 0; q < 8; q++) {
            uint32_t off = sw_off(rtid, q);
            *(uint4*)(smem + AH + off) = make_uint4(hi[4*q], hi[4*q+1], hi[4*q+2], hi[4*q+3]);
            *(uint4*)(smem + AL + off) = make_uint4(lo[4*q], lo[4*q+1], lo[4*q+2], lo[4*q+3]);
        }
    }
    __syncthreads();

    float acc[2][8][4];
    uint32_t ahr[2][4][4], alr[2][4][4];   // register A fragments (hi/lo)

    // ================= layer 1 (A from smem) =================
#pragma unroll
    for (int mt = 0; mt < 2; mt++)
#pragma unroll
        for (int j = 0; j < 8; j++)
#pragma unroll
            for (int v = 0; v < 4; v++) acc[mt][j][v] = 0.f;

#pragma unroll
    for (int ks = 0; ks < 4; ks++) {
        uint32_t ahs[2][4], als[2][4];
#pragma unroll
        for (int mt = 0; mt < 2; mt++) {
            uint32_t off = sw_off(wbase + mt * 16 + a_rl, ks * 2 + a_c4h);
            ldsm4(ahs[mt], sb + AH + off);
            ldsm4(als[mt], sb + AL + off);
        }
#pragma unroll
        for (int p = 0; p < 4; p++) {
            uint32_t wh[4], wl[4];
            uint32_t off = sw_off(p * 16 + b_nl, ks * 2 + b_c4h);
            ldsm4(wh, sb + SM_W1H + off);
            ldsm4(wl, sb + SM_W1L + off);
#pragma unroll
            for (int mt = 0; mt < 2; mt++) {
                mma16816(acc[mt][2*p],   ahs[mt], wh[0], wh[1]);
                mma16816(acc[mt][2*p],   ahs[mt], wl[0], wl[1]);
                mma16816(acc[mt][2*p],   als[mt], wh[0], wh[1]);
                mma16816(acc[mt][2*p+1], ahs[mt], wh[2], wh[3]);
                mma16816(acc[mt][2*p+1], ahs[mt], wl[2], wl[3]);
                mma16816(acc[mt][2*p+1], als[mt], wh[2], wh[3]);
            }
        }
    }

    // epilogue 1: bias+relu+split -> register A fragments
    {
        const float* bias = (const float*)(smem + SM_B1);
#pragma unroll
        for (int mt = 0; mt < 2; mt++)
#pragma unroll
            for (int j = 0; j < 8; j++) {
                int cb = 8 * j + c2l;
                float v0 = fmaxf(acc[mt][j][0] + bias[cb],     0.f);
                float v1 = fmaxf(acc[mt][j][1] + bias[cb + 1], 0.f);
                float v2 = fmaxf(acc[mt][j][2] + bias[cb],     0.f);
                float v3 = fmaxf(acc[mt][j][3] + bias[cb + 1], 0.f);
                uint32_t h01, l01, h23, l23;
                split2(v0, v1, h01, l01);
                split2(v2, v3, h23, l23);
                int s = j >> 1, hf = j & 1;
                ahr[mt][s][2*hf]   = h01; ahr[mt][s][2*hf+1] = h23;
                alr[mt][s][2*hf]   = l01; alr[mt][s][2*hf+1] = l23;
            }
    }

    // ================= layer 2 (A from registers) =================
#pragma unroll
    for (int mt = 0; mt < 2; mt++)
#pragma unroll
        for (int j = 0; j < 8; j++)
#pragma unroll
            for (int v = 0; v < 4; v++) acc[mt][j][v] = 0.f;

#pragma unroll
    for (int ks = 0; ks < 4; ks++) {
#pragma unroll
        for (int p = 0; p < 4; p++) {
            uint32_t wh[4], wl[4];
            uint32_t off = sw_off(p * 16 + b_nl, ks * 2 + b_c4h);
            ldsm4(wh, sb + SM_W2H + off);
            ldsm4(wl, sb + SM_W2L + off);
#pragma unroll
            for (int mt = 0; mt < 2; mt++) {
                mma16816(acc[mt][2*p],   ahr[mt][ks], wh[0], wh[1]);
                mma16816(acc[mt][2*p],   ahr[mt][ks], wl[0], wl[1]);
                mma16816(acc[mt][2*p],   alr[mt][ks], wh[0], wh[1]);
                mma16816(acc[mt][2*p+1], ahr[mt][ks], wh[2], wh[3]);
                mma16816(acc[mt][2*p+1], ahr[mt][ks], wl[2], wl[3]);
                mma16816(acc[mt][2*p+1], alr[mt][ks], wh[2], wh[3]);
            }
        }
    }

    // epilogue 2 -> overwrite register A fragments
    {
        const float* bias = (const float*)(smem + SM_B2);
#pragma unroll
        for (int mt = 0; mt < 2; mt++)
#pragma unroll
            for (int j = 0; j < 8; j++) {
                int cb = 8 * j + c2l;
                float v0 = fmaxf(acc[mt][j][0] + bias[cb],     0.f);
                float v1 = fmaxf(acc[mt][j][1] + bias[cb + 1], 0.f);
                float v2 = fmaxf(acc[mt][j][2] + bias[cb],     0.f);
                float v3 = fmaxf(acc[mt][j][3] + bias[cb + 1], 0.f);
                uint32_t h01, l01, h23, l23;
                split2(v0, v1, h01, l01);
                split2(v2, v3, h23, l23);
                int s = j >> 1, hf = j & 1;
                ahr[mt][s][2*hf]   = h01; ahr[mt][s][2*hf+1] = h23;
                alr[mt][s][2*hf]   = l01; alr[mt][s][2*hf+1] = l23;
            }
    }

    // ================= layer 3 (N=32, cols 0..16 valid) =================
#pragma unroll
    for (int mt = 0; mt < 2; mt++)
#pragma unroll
        for (int j = 0; j < 4; j++)
#pragma unroll
            for (int v = 0; v < 4; v++) acc[mt][j][v] = 0.f;

#pragma unroll
    for (int ks = 0; ks < 4; ks++) {
#pragma unroll
        for (int p = 0; p < 2; p++) {
            uint32_t wh[4], wl[4];
            uint32_t off = sw_off(p * 16 + b_nl, ks * 2 + b_c4h);
            ldsm4(wh, sb + SM_WOH + off);
            ldsm4(wl, sb + SM_WOL + off);
#pragma unroll
            for (int mt = 0; mt < 2; mt++) {
                mma16816(acc[mt][2*p],   ahr[mt][ks], wh[0], wh[1]);
                mma16816(acc[mt][2*p],   ahr[mt][ks], wl[0], wl[1]);
                mma16816(acc[mt][2*p],   alr[mt][ks], wh[0], wh[1]);
                mma16816(acc[mt][2*p+1], ahr[mt][ks], wh[2], wh[3]);
                mma16816(acc[mt][2*p+1], ahr[mt][ks], wl[2], wl[3]);
                mma16816(acc[mt][2*p+1], alr[mt][ks], wh[2], wh[3]);
            }
        }
    }

    // A tiles dead (layers 2-3 ran from registers); alias OUT staging onto AH
    __syncthreads();
    {
        const float* bos = (const float*)(smem + SM_BO);
        float* po = (float*)(smem + AH);   // 128 rows x 20 f32
#pragma unroll
        for (int mt = 0; mt < 2; mt++)
#pragma unroll
            for (int j = 0; j < 3; j++) {
                int cb = 8 * j + c2l;
                if (cb <= 16) {
                    int r0 = wbase + mt * 16 + (lid >> 2);
                    float bv0 = bos[cb];
                    float bv1 = (cb + 1 < 17) ? bos[cb + 1] : 0.f;
                    po[r0 * 20 + cb]           = acc[mt][j][0] + bv0;
                    po[r0 * 20 + cb + 1]       = acc[mt][j][1] + bv1;
                    po[(r0 + 8) * 20 + cb]     = acc[mt][j][2] + bv0;
                    po[(r0 + 8) * 20 + cb + 1] = acc[mt][j][3] + bv1;
                }
            }
    }
    __syncthreads();

    // ---------------- per-sample tail ----------------
    {
        const float* myo = (const float*)(smem + AH) + rtid * 20;
        const float sigma = fmaxf(myo[0], 0.f);
        const float* wrgb = (const float*)(smem + SM_WRGB);
        const float* brg  = (const float*)(smem + SM_BRGB);
        float rgbv[3];
#pragma unroll
        for (int cc = 0; cc < 3; cc++) {
            float r = brg[cc];
#pragma unroll
            for (int k = 0; k < 16; k++) r = fmaf(myo[1 + k], wrgb[k * 3 + cc], r);
            rgbv[cc] = 1.0f / (1.0f + expf(-r));
        }

        const float alpha = 1.0f - expf(-sigma * dtv);
        const float q     = (1.0f - alpha) + 1e-10f;

        float p = q;
#pragma unroll
        for (int d = 1; d < 32; d <<= 1) {
            float u = __shfl_up_sync(0xffffffffu, p, d);
            if (lid >= d) p *= u;
        }
        __shared__ float wtot[RAYS_PER_CTA][4];
        if (lid == 31) wtot[rayi][wray] = p;
        __syncthreads();
        float pre = 1.0f;
        for (int w = 0; w < wray; w++) pre *= wtot[rayi][w];
        float excl = __shfl_up_sync(0xffffffffu, p, 1);
        if (lid == 0) excl = 1.0f;
        const float T    = pre * excl;
        const float incl = pre * p;
        const float wgt  = (T > 1e-4f) ? (T * alpha) : 0.f;

        float v0 = wgt * rgbv[0], v1 = wgt * rgbv[1], v2 = wgt * rgbv[2];
#pragma unroll
        for (int off = 16; off > 0; off >>= 1) {
            v0 += __shfl_down_sync(0xffffffffu, v0, off);
            v1 += __shfl_down_sync(0xffffffffu, v1, off);
            v2 += __shfl_down_sync(0xffffffffu, v2, off);
        }
        __shared__ float redc[RAYS_PER_CTA][4][3];
        if (lid == 0) { redc[rayi][wray][0] = v0; redc[rayi][wray][1] = v1; redc[rayi][wray][2] = v2; }
        if (rtid == SS - 1) out[3 * n + ray] = incl;
        __syncthreads();
        if (rtid == 0) {
            out[ray * 3 + 0] = redc[rayi][0][0] + redc[rayi][1][0] + redc[rayi][2][0] + redc[rayi][3][0];
            out[ray * 3 + 1] = redc[rayi][0][1] + redc[rayi][1][1] + redc[rayi][2][1] + redc[rayi][3][1];
            out[ray * 3 + 2] = redc[rayi][0][2] + redc[rayi][1][2] + redc[rayi][2][2] + redc[rayi][3][2];
        }
    }
    __syncthreads();   // protect AH/redc reuse across loop iterations

    }  // pair loop
}

extern "C" void kernel_launch(void* const* d_in, const int* in_sizes, int n_in,
                              void* d_out, int out_size) {
    const float* ox   = (const float*)d_in[0];
    const float* oy   = (const float*)d_in[1];
    const float* oz   = (const float*)d_in[2];
    const float* dxv  = (const float*)d_in[3];
    const float* dyv  = (const float*)d_in[4];
    const float* dzv  = (const float*)d_in[5];
    const float* tmin = (const float*)d_in[6];
    const float* tmax = (const float*)d_in[7];
    const float* W1   = (const float*)d_in[8];
    const float* b1   = (const float*)d_in[9];
    const float* W2   = (const float*)d_in[10];
    const float* b2   = (const float*)d_in[11];
    const float* Wo   = (const float*)d_in[12];
    const float* bo   = (const float*)d_in[13];
    const float* Wrgb = (const float*)d_in[14];
    const float* brgb = (const float*)d_in[15];
    float* out = (float*)d_out;
    const int n = in_sizes[0];

    cudaFuncSetAttribute(nerf_mma_kernel, cudaFuncAttributeMaxDynamicSharedMemorySize, SM_TOTAL);

    prep_kernel<<<1, 256>>>(tmin, tmax, W1, W2, Wo, n);

    int npairs = n / RAYS_PER_CTA;
    int grid = NCTA < npairs ? NCTA : npairs;
    nerf_mma_kernel<<<grid, TPB, SM_TOTAL>>>(
        ox, oy, oz, dxv, dyv, dzv, tmin, tmax,
        b1, b2, bo, Wrgb, brgb, out, n);
}

// round 8
// speedup vs baseline: 1.3040x; 1.3040x over previous
#include <cuda_runtime.h>
#include <cuda_bf16.h>
#include <cstdint>
#include <math.h>

#define SS    128
#define LFREQ 10

__device__ float g_dt;
__device__ __align__(16) unsigned char g_wbuf[40960];   // pre-swizzled bf16 hi/lo weights

#define GW_W1H 0
#define GW_W1L 8192
#define GW_W2H 16384
#define GW_W2L 24576
#define GW_WOH 32768
#define GW_WOL 36864

// ---------------- helpers ----------------
__device__ __forceinline__ uint32_t smem_to_u32(const void* p) {
    uint32_t a;
    asm("{ .reg .u64 t; cvta.to.shared.u64 t, %1; cvt.u32.u64 %0, t; }" : "=r"(a) : "l"(p));
    return a;
}

__device__ __forceinline__ void ldsm4(uint32_t* r, uint32_t addr) {
    asm volatile("ldmatrix.sync.aligned.m8n8.x4.shared.b16 {%0,%1,%2,%3}, [%4];"
        : "=r"(r[0]), "=r"(r[1]), "=r"(r[2]), "=r"(r[3]) : "r"(addr));
}

__device__ __forceinline__ void mma16816(float* d, const uint32_t* a, uint32_t b0, uint32_t b1) {
    asm volatile("mma.sync.aligned.m16n8k16.row.col.f32.bf16.bf16.f32 "
        "{%0,%1,%2,%3}, {%4,%5,%6,%7}, {%8,%9}, {%0,%1,%2,%3};"
        : "+f"(d[0]), "+f"(d[1]), "+f"(d[2]), "+f"(d[3])
        : "r"(a[0]), "r"(a[1]), "r"(a[2]), "r"(a[3]), "r"(b0), "r"(b1));
}

__device__ __forceinline__ void split1(float x, uint16_t& h, uint16_t& l) {
    uint16_t hb = __bfloat16_as_ushort(__float2bfloat16_rn(x));
    float r = __uint_as_float(((uint32_t)hb) << 16);
    uint16_t lb = __bfloat16_as_ushort(__float2bfloat16_rn(x - r));
    h = hb; l = lb;
}
__device__ __forceinline__ void split2(float a, float b, uint32_t& h, uint32_t& l) {
    uint16_t ha, la, hb2, lb2;
    split1(a, ha, la); split1(b, hb2, lb2);
    h = (uint32_t)ha | ((uint32_t)hb2 << 16);
    l = (uint32_t)la | ((uint32_t)lb2 << 16);
}

// swizzled tile byte offset: row-major, 128B rows, 16B granules XORed
__device__ __forceinline__ uint32_t sw_off(int row, int c4) {
    return (uint32_t)(row * 128 + ((c4 ^ (row & 7)) << 4));
}

#define BARSYNC(id, cnt) asm volatile("bar.sync %0, %1;" :: "r"(id), "r"(cnt) : "memory")

// ---------------- SMEM layout (byte offsets) ----------------
#define SM_B1    0
#define SM_B2    256
#define SM_BO    512
#define SM_WRGB  640
#define SM_BRGB  832
#define SM_W     1024
#define SM_W1H   (SM_W + GW_W1H)
#define SM_W1L   (SM_W + GW_W1L)
#define SM_W2H   (SM_W + GW_W2H)
#define SM_W2L   (SM_W + GW_W2L)
#define SM_WOH   (SM_W + GW_WOH)
#define SM_WOL   (SM_W + GW_WOL)
#define SM_A     41984   // 2 rays x (16384 hi + 16384 lo)
#define SM_TOTAL (41984 + 65536)

#define TPB 256
#define RAYS_PER_CTA 2

// -------- prep: dt reduction + weight conversion (one CTA) --------
__global__ void prep_kernel(const float* __restrict__ tmin, const float* __restrict__ tmax,
                            const float* __restrict__ W1, const float* __restrict__ W2,
                            const float* __restrict__ Wo, int n) {
    __shared__ float red[256];
    int tid = threadIdx.x;
    float acc = 0.f;
    for (int i = tid; i < n; i += 256) acc += tmax[i] - tmin[i];
    red[tid] = acc;
    __syncthreads();
    for (int s = 128; s > 0; s >>= 1) {
        if (tid < s) red[tid] += red[tid + s];
        __syncthreads();
    }
    if (tid == 0) g_dt = (red[0] / (float)n) / (float)SS;

    for (int idx = tid; idx < 64 * 64; idx += 256) {
        int nn = idx >> 6, k = idx & 63;
        float w = (k < 63) ? W1[k * 64 + nn] : 0.f;
        uint16_t h, l; split1(w, h, l);
        uint32_t off = sw_off(nn, k >> 3) + (k & 7) * 2;
        *(uint16_t*)(g_wbuf + GW_W1H + off) = h;
        *(uint16_t*)(g_wbuf + GW_W1L + off) = l;
    }
    for (int idx = tid; idx < 64 * 64; idx += 256) {
        int nn = idx >> 6, k = idx & 63;
        float w = W2[k * 64 + nn];
        uint16_t h, l; split1(w, h, l);
        uint32_t off = sw_off(nn, k >> 3) + (k & 7) * 2;
        *(uint16_t*)(g_wbuf + GW_W2H + off) = h;
        *(uint16_t*)(g_wbuf + GW_W2L + off) = l;
    }
    for (int idx = tid; idx < 32 * 64; idx += 256) {
        int nn = idx >> 6, k = idx & 63;
        float w = (nn < 17) ? Wo[k * 17 + nn] : 0.f;
        uint16_t h, l; split1(w, h, l);
        uint32_t off = sw_off(nn, k >> 3) + (k & 7) * 2;
        *(uint16_t*)(g_wbuf + GW_WOH + off) = h;
        *(uint16_t*)(g_wbuf + GW_WOL + off) = l;
    }
}

__global__ void __launch_bounds__(TPB, 2)
nerf_mma_kernel(const float* __restrict__ ox, const float* __restrict__ oy,
                const float* __restrict__ oz, const float* __restrict__ dxv,
                const float* __restrict__ dyv, const float* __restrict__ dzv,
                const float* __restrict__ tmin, const float* __restrict__ tmax,
                const float* __restrict__ b1, const float* __restrict__ b2,
                const float* __restrict__ bo,
                const float* __restrict__ Wrgb, const float* __restrict__ brgb,
                float* __restrict__ out, int n)
{
    extern __shared__ __align__(1024) char smem[];
    const uint32_t sb = smem_to_u32(smem);
    const int tid  = threadIdx.x;
    const int rayi = tid >> 7;
    const int rtid = tid & 127;
    const int lid  = tid & 31;
    const int wray = (tid >> 5) & 3;
    const int wbase = wray * 32;
    const uint32_t AH = SM_A + rayi * 32768;
    const uint32_t AL = AH + 16384;
    // per-warp private OUT staging inside own A-row region: 32 rows x 20 f32 = 2560B < 4096B
    const uint32_t PO = AH + (uint32_t)wbase * 128;

    // ---- stage weights in shared ----
    {
        const uint4* src = (const uint4*)g_wbuf;
        uint4* dst = (uint4*)(smem + SM_W);
        for (int i = tid; i < 2560; i += TPB) dst[i] = src[i];
        float* s = (float*)smem;
        for (int i = tid; i < 64; i += TPB) s[(SM_B1 >> 2) + i] = b1[i];
        for (int i = tid; i < 64; i += TPB) s[(SM_B2 >> 2) + i] = b2[i];
        for (int i = tid; i < 17; i += TPB) s[(SM_BO >> 2) + i] = bo[i];
        for (int i = tid; i < 48; i += TPB) s[(SM_WRGB >> 2) + i] = Wrgb[i];
        for (int i = tid; i < 3;  i += TPB) s[(SM_BRGB >> 2) + i] = brgb[i];
    }

    // ---- positional encodings -> A tile (row = sample = rtid; warp-local rows) ----
    const int ray = blockIdx.x * RAYS_PER_CTA + rayi;
    const float tmn = tmin[ray], tmx = tmax[ray];
    const float t  = fmaf((float)rtid * (1.0f / (float)(SS - 1)), tmx - tmn, tmn);
    {
        float e[64];
        e[0] = fmaf(dxv[ray], t, ox[ray]);
        e[1] = fmaf(dyv[ray], t, oy[ray]);
        e[2] = fmaf(dzv[ray], t, oz[ray]);
        e[63] = 0.f;
#pragma unroll 1
        for (int c = 0; c < 3; c++) {
            float sv, cv;
            sincosf(e[c], &sv, &cv);
#pragma unroll
            for (int f = 0; f < LFREQ; f++) {
                e[3 + 20 * c + f]      = sv;
                e[3 + 20 * c + 10 + f] = cv;
                float ns = 2.0f * sv * cv;
                float nc = fmaf(cv, cv, -(sv * sv));
                sv = ns; cv = nc;
            }
        }
        uint32_t hi[32], lo[32];
#pragma unroll
        for (int j = 0; j < 32; j++) split2(e[2 * j], e[2 * j + 1], hi[j], lo[j]);
#pragma unroll
        for (int q = 0; q < 8; q++) {
            uint32_t off = sw_off(rtid, q);
            *(uint4*)(smem + AH + off) = make_uint4(hi[4*q], hi[4*q+1], hi[4*q+2], hi[4*q+3]);
            *(uint4*)(smem + AL + off) = make_uint4(lo[4*q], lo[4*q+1], lo[4*q+2], lo[4*q+3]);
        }
    }
    // weights needed by all warps; A rows are warp-local but weights cross-warp
    __syncthreads();

    // lane-derived ldmatrix coordinates
    const int lj = lid >> 3, lr = lid & 7;
    const int a_rl  = ((lj & 1) << 3) + lr;
    const int a_c4h = lj >> 1;
    const int b_nl  = ((lj >> 1) << 3) + lr;
    const int b_c4h = lj & 1;
    const int c2l   = 2 * (lid & 3);

    float acc[2][8][4];
    uint32_t ahr[2][4][4], alr[2][4][4];   // register A fragments (hi/lo)

    // ================= layer 1 (A from smem, warp-own rows) =================
#pragma unroll
    for (int mt = 0; mt < 2; mt++)
#pragma unroll
        for (int j = 0; j < 8; j++)
#pragma unroll
            for (int v = 0; v < 4; v++) acc[mt][j][v] = 0.f;

#pragma unroll
    for (int ks = 0; ks < 4; ks++) {
        uint32_t ahs[2][4], als[2][4];
#pragma unroll
        for (int mt = 0; mt < 2; mt++) {
            uint32_t off = sw_off(wbase + mt * 16 + a_rl, ks * 2 + a_c4h);
            ldsm4(ahs[mt], sb + AH + off);
            ldsm4(als[mt], sb + AL + off);
        }
#pragma unroll
        for (int p = 0; p < 4; p++) {
            uint32_t wh[4], wl[4];
            uint32_t off = sw_off(p * 16 + b_nl, ks * 2 + b_c4h);
            ldsm4(wh, sb + SM_W1H + off);
            ldsm4(wl, sb + SM_W1L + off);
#pragma unroll
            for (int mt = 0; mt < 2; mt++) {
                mma16816(acc[mt][2*p],   ahs[mt], wh[0], wh[1]);
                mma16816(acc[mt][2*p],   ahs[mt], wl[0], wl[1]);
                mma16816(acc[mt][2*p],   als[mt], wh[0], wh[1]);
                mma16816(acc[mt][2*p+1], ahs[mt], wh[2], wh[3]);
                mma16816(acc[mt][2*p+1], ahs[mt], wl[2], wl[3]);
                mma16816(acc[mt][2*p+1], als[mt], wh[2], wh[3]);
            }
        }
    }

    // epilogue 1: bias+relu+split -> register A fragments
    {
        const float* bias = (const float*)(smem + SM_B1);
#pragma unroll
        for (int mt = 0; mt < 2; mt++)
#pragma unroll
            for (int j = 0; j < 8; j++) {
                int cb = 8 * j + c2l;
                float v0 = fmaxf(acc[mt][j][0] + bias[cb],     0.f);
                float v1 = fmaxf(acc[mt][j][1] + bias[cb + 1], 0.f);
                float v2 = fmaxf(acc[mt][j][2] + bias[cb],     0.f);
                float v3 = fmaxf(acc[mt][j][3] + bias[cb + 1], 0.f);
                uint32_t h01, l01, h23, l23;
                split2(v0, v1, h01, l01);
                split2(v2, v3, h23, l23);
                int s = j >> 1, hf = j & 1;
                ahr[mt][s][2*hf]   = h01; ahr[mt][s][2*hf+1] = h23;
                alr[mt][s][2*hf]   = l01; alr[mt][s][2*hf+1] = l23;
            }
    }

    // ================= layer 2 (A from registers) =================
#pragma unroll
    for (int mt = 0; mt < 2; mt++)
#pragma unroll
        for (int j = 0; j < 8; j++)
#pragma unroll
            for (int v = 0; v < 4; v++) acc[mt][j][v] = 0.f;

#pragma unroll
    for (int ks = 0; ks < 4; ks++) {
#pragma unroll
        for (int p = 0; p < 4; p++) {
            uint32_t wh[4], wl[4];
            uint32_t off = sw_off(p * 16 + b_nl, ks * 2 + b_c4h);
            ldsm4(wh, sb + SM_W2H + off);
            ldsm4(wl, sb + SM_W2L + off);
#pragma unroll
            for (int mt = 0; mt < 2; mt++) {
                mma16816(acc[mt][2*p],   ahr[mt][ks], wh[0], wh[1]);
                mma16816(acc[mt][2*p],   ahr[mt][ks], wl[0], wl[1]);
                mma16816(acc[mt][2*p],   alr[mt][ks], wh[0], wh[1]);
                mma16816(acc[mt][2*p+1], ahr[mt][ks], wh[2], wh[3]);
                mma16816(acc[mt][2*p+1], ahr[mt][ks], wl[2], wl[3]);
                mma16816(acc[mt][2*p+1], alr[mt][ks], wh[2], wh[3]);
            }
        }
    }

    // epilogue 2 -> overwrite register A fragments
    {
        const float* bias = (const float*)(smem + SM_B2);
#pragma unroll
        for (int mt = 0; mt < 2; mt++)
#pragma unroll
            for (int j = 0; j < 8; j++) {
                int cb = 8 * j + c2l;
                float v0 = fmaxf(acc[mt][j][0] + bias[cb],     0.f);
                float v1 = fmaxf(acc[mt][j][1] + bias[cb + 1], 0.f);
                float v2 = fmaxf(acc[mt][j][2] + bias[cb],     0.f);
                float v3 = fmaxf(acc[mt][j][3] + bias[cb + 1], 0.f);
                uint32_t h01, l01, h23, l23;
                split2(v0, v1, h01, l01);
                split2(v2, v3, h23, l23);
                int s = j >> 1, hf = j & 1;
                ahr[mt][s][2*hf]   = h01; ahr[mt][s][2*hf+1] = h23;
                alr[mt][s][2*hf]   = l01; alr[mt][s][2*hf+1] = l23;
            }
    }

    // ================= layer 3 (N=32, cols 0..16 valid) =================
#pragma unroll
    for (int mt = 0; mt < 2; mt++)
#pragma unroll
        for (int j = 0; j < 4; j++)
#pragma unroll
            for (int v = 0; v < 4; v++) acc[mt][j][v] = 0.f;

#pragma unroll
    for (int ks = 0; ks < 4; ks++) {
#pragma unroll
        for (int p = 0; p < 2; p++) {
            uint32_t wh[4], wl[4];
            uint32_t off = sw_off(p * 16 + b_nl, ks * 2 + b_c4h);
            ldsm4(wh, sb + SM_WOH + off);
            ldsm4(wl, sb + SM_WOL + off);
#pragma unroll
            for (int mt = 0; mt < 2; mt++) {
                mma16816(acc[mt][2*p],   ahr[mt][ks], wh[0], wh[1]);
                mma16816(acc[mt][2*p],   ahr[mt][ks], wl[0], wl[1]);
                mma16816(acc[mt][2*p],   alr[mt][ks], wh[0], wh[1]);
                mma16816(acc[mt][2*p+1], ahr[mt][ks], wh[2], wh[3]);
                mma16816(acc[mt][2*p+1], ahr[mt][ks], wl[2], wl[3]);
                mma16816(acc[mt][2*p+1], alr[mt][ks], wh[2], wh[3]);
            }
        }
    }

    // OUT staging into warp-private region of the (now dead for this warp) A tile.
    // Warp w's region PO..PO+2560 sits inside its OWN A rows -> no cross-warp hazard.
    __syncwarp();
    {
        const float* bos = (const float*)(smem + SM_BO);
        float* po = (float*)(smem + PO);   // local rows 0..31, stride 20 f32
#pragma unroll
        for (int mt = 0; mt < 2; mt++)
#pragma unroll
            for (int j = 0; j < 3; j++) {
                int cb = 8 * j + c2l;
                if (cb <= 16) {
                    int r0 = mt * 16 + (lid >> 2);   // 0..23
                    float bv0 = bos[cb];
                    float bv1 = (cb + 1 < 17) ? bos[cb + 1] : 0.f;
                    po[r0 * 20 + cb]           = acc[mt][j][0] + bv0;
                    po[r0 * 20 + cb + 1]       = acc[mt][j][1] + bv1;
                    po[(r0 + 8) * 20 + cb]     = acc[mt][j][2] + bv0;
                    po[(r0 + 8) * 20 + cb + 1] = acc[mt][j][3] + bv1;
                }
            }
    }
    __syncwarp();

    // ---------------- per-sample tail ----------------
    {
        const float* myo = (const float*)(smem + PO) + (rtid - wbase) * 20;
        const float sigma = fmaxf(myo[0], 0.f);
        const float* wrgb = (const float*)(smem + SM_WRGB);
        const float* brg  = (const float*)(smem + SM_BRGB);
        float rgbv[3];
#pragma unroll
        for (int cc = 0; cc < 3; cc++) {
            float r = brg[cc];
#pragma unroll
            for (int k = 0; k < 16; k++) r = fmaf(myo[1 + k], wrgb[k * 3 + cc], r);
            rgbv[cc] = 1.0f / (1.0f + expf(-r));
        }

        const float dtv   = g_dt;
        const float alpha = 1.0f - expf(-sigma * dtv);
        const float q     = (1.0f - alpha) + 1e-10f;

        float p = q;
#pragma unroll
        for (int d = 1; d < 32; d <<= 1) {
            float u = __shfl_up_sync(0xffffffffu, p, d);
            if (lid >= d) p *= u;
        }
        __shared__ float wtot[RAYS_PER_CTA][4];
        if (lid == 31) wtot[rayi][wray] = p;
        BARSYNC(1 + rayi, 128);                    // ray-scoped barrier
        float pre = 1.0f;
        for (int w = 0; w < wray; w++) pre *= wtot[rayi][w];
        float excl = __shfl_up_sync(0xffffffffu, p, 1);
        if (lid == 0) excl = 1.0f;
        const float T    = pre * excl;
        const float incl = pre * p;
        const float wgt  = (T > 1e-4f) ? (T * alpha) : 0.f;

        float v0 = wgt * rgbv[0], v1 = wgt * rgbv[1], v2 = wgt * rgbv[2];
#pragma unroll
        for (int off = 16; off > 0; off >>= 1) {
            v0 += __shfl_down_sync(0xffffffffu, v0, off);
            v1 += __shfl_down_sync(0xffffffffu, v1, off);
            v2 += __shfl_down_sync(0xffffffffu, v2, off);
        }
        __shared__ float redc[RAYS_PER_CTA][4][3];
        if (lid == 0) { redc[rayi][wray][0] = v0; redc[rayi][wray][1] = v1; redc[rayi][wray][2] = v2; }
        if (rtid == SS - 1) out[3 * n + ray] = incl;
        BARSYNC(1 + rayi, 128);                    // ray-scoped barrier
        if (rtid == 0) {
            out[ray * 3 + 0] = redc[rayi][0][0] + redc[rayi][1][0] + redc[rayi][2][0] + redc[rayi][3][0];
            out[ray * 3 + 1] = redc[rayi][0][1] + redc[rayi][1][1] + redc[rayi][2][1] + redc[rayi][3][1];
            out[ray * 3 + 2] = redc[rayi][0][2] + redc[rayi][1][2] + redc[rayi][2][2] + redc[rayi][3][2];
        }
    }
}

extern "C" void kernel_launch(void* const* d_in, const int* in_sizes, int n_in,
                              void* d_out, int out_size) {
    const float* ox   = (const float*)d_in[0];
    const float* oy   = (const float*)d_in[1];
    const float* oz   = (const float*)d_in[2];
    const float* dxv  = (const float*)d_in[3];
    const float* dyv  = (const float*)d_in[4];
    const float* dzv  = (const float*)d_in[5];
    const float* tmin = (const float*)d_in[6];
    const float* tmax = (const float*)d_in[7];
    const float* W1   = (const float*)d_in[8];
    const float* b1   = (const float*)d_in[9];
    const float* W2   = (const float*)d_in[10];
    const float* b2   = (const float*)d_in[11];
    const float* Wo   = (const float*)d_in[12];
    const float* bo   = (const float*)d_in[13];
    const float* Wrgb = (const float*)d_in[14];
    const float* brgb = (const float*)d_in[15];
    float* out = (float*)d_out;
    const int n = in_sizes[0];

    cudaFuncSetAttribute(nerf_mma_kernel, cudaFuncAttributeMaxDynamicSharedMemorySize, SM_TOTAL);

    prep_kernel<<<1, 256>>>(tmin, tmax, W1, W2, Wo, n);
    nerf_mma_kernel<<<n / RAYS_PER_CTA, TPB, SM_TOTAL>>>(
        ox, oy, oz, dxv, dyv, dzv, tmin, tmax,
        b1, b2, bo, Wrgb, brgb, out, n);
}

// round 9
// speedup vs baseline: 2.0738x; 1.5904x over previous
#include <cuda_runtime.h>
#include <cuda_bf16.h>
#include <cstdint>
#include <math.h>

#define SS    128
#define LFREQ 10

__device__ float g_dt;
__device__ __align__(16) unsigned char g_wbuf[40960];   // pre-swizzled bf16 hi/lo weights

#define GW_W1H 0
#define GW_W1L 8192
#define GW_W2H 16384
#define GW_W2L 24576
#define GW_WOH 32768
#define GW_WOL 36864

// ---------------- helpers ----------------
__device__ __forceinline__ uint32_t smem_to_u32(const void* p) {
    uint32_t a;
    asm("{ .reg .u64 t; cvta.to.shared.u64 t, %1; cvt.u32.u64 %0, t; }" : "=r"(a) : "l"(p));
    return a;
}

__device__ __forceinline__ void ldsm4(uint32_t* r, uint32_t addr) {
    asm volatile("ldmatrix.sync.aligned.m8n8.x4.shared.b16 {%0,%1,%2,%3}, [%4];"
        : "=r"(r[0]), "=r"(r[1]), "=r"(r[2]), "=r"(r[3]) : "r"(addr));
}

__device__ __forceinline__ void mma16816(float* d, const uint32_t* a, uint32_t b0, uint32_t b1) {
    asm volatile("mma.sync.aligned.m16n8k16.row.col.f32.bf16.bf16.f32 "
        "{%0,%1,%2,%3}, {%4,%5,%6,%7}, {%8,%9}, {%0,%1,%2,%3};"
        : "+f"(d[0]), "+f"(d[1]), "+f"(d[2]), "+f"(d[3])
        : "r"(a[0]), "r"(a[1]), "r"(a[2]), "r"(a[3]), "r"(b0), "r"(b1));
}

__device__ __forceinline__ void split1(float x, uint16_t& h, uint16_t& l) {
    uint16_t hb = __bfloat16_as_ushort(__float2bfloat16_rn(x));
    float r = __uint_as_float(((uint32_t)hb) << 16);
    uint16_t lb = __bfloat16_as_ushort(__float2bfloat16_rn(x - r));
    h = hb; l = lb;
}

// packed split: h = bf16x2(a,b), l = bf16x2 of residuals (2 cvts + 2 subs)
__device__ __forceinline__ void split2(float a, float b, uint32_t& h, uint32_t& l) {
    uint32_t hh;
    asm("cvt.rn.bf16x2.f32 %0, %1, %2;" : "=r"(hh) : "f"(b), "f"(a));
    float ra = __uint_as_float(hh << 16);
    float rb = __uint_as_float(hh & 0xFFFF0000u);
    float da = a - ra, db = b - rb;
    uint32_t ll;
    asm("cvt.rn.bf16x2.f32 %0, %1, %2;" : "=r"(ll) : "f"(db), "f"(da));
    h = hh; l = ll;
}

// swizzled tile byte offset: row-major, 128B rows, 16B granules XORed
__device__ __forceinline__ uint32_t sw_off(int row, int c4) {
    return (uint32_t)(row * 128 + ((c4 ^ (row & 7)) << 4));
}

// ---------------- SMEM layout (byte offsets) ----------------
#define SM_B1    0
#define SM_B2    256
#define SM_BO    512
#define SM_WRGB  640
#define SM_BRGB  832
#define SM_W     1024
#define SM_W1H   (SM_W + GW_W1H)
#define SM_W1L   (SM_W + GW_W1L)
#define SM_W2H   (SM_W + GW_W2H)
#define SM_W2L   (SM_W + GW_W2L)
#define SM_WOH   (SM_W + GW_WOH)
#define SM_WOL   (SM_W + GW_WOL)
#define SM_A     41984   // 2 rays x (16384 hi + 16384 lo)
#define SM_TOTAL (41984 + 65536)

#define TPB 256
#define RAYS_PER_CTA 2

// -------- prep: dt reduction + weight conversion (one CTA) --------
__global__ void prep_kernel(const float* __restrict__ tmin, const float* __restrict__ tmax,
                            const float* __restrict__ W1, const float* __restrict__ W2,
                            const float* __restrict__ Wo, int n) {
    __shared__ float red[256];
    int tid = threadIdx.x;
    float acc = 0.f;
    for (int i = tid; i < n; i += 256) acc += tmax[i] - tmin[i];
    red[tid] = acc;
    __syncthreads();
    for (int s = 128; s > 0; s >>= 1) {
        if (tid < s) red[tid] += red[tid + s];
        __syncthreads();
    }
    if (tid == 0) g_dt = (red[0] / (float)n) / (float)SS;

    for (int idx = tid; idx < 64 * 64; idx += 256) {
        int nn = idx >> 6, k = idx & 63;
        float w = (k < 63) ? W1[k * 64 + nn] : 0.f;
        uint16_t h, l; split1(w, h, l);
        uint32_t off = sw_off(nn, k >> 3) + (k & 7) * 2;
        *(uint16_t*)(g_wbuf + GW_W1H + off) = h;
        *(uint16_t*)(g_wbuf + GW_W1L + off) = l;
    }
    for (int idx = tid; idx < 64 * 64; idx += 256) {
        int nn = idx >> 6, k = idx & 63;
        float w = W2[k * 64 + nn];
        uint16_t h, l; split1(w, h, l);
        uint32_t off = sw_off(nn, k >> 3) + (k & 7) * 2;
        *(uint16_t*)(g_wbuf + GW_W2H + off) = h;
        *(uint16_t*)(g_wbuf + GW_W2L + off) = l;
    }
    for (int idx = tid; idx < 32 * 64; idx += 256) {
        int nn = idx >> 6, k = idx & 63;
        float w = (nn < 17) ? Wo[k * 17 + nn] : 0.f;
        uint16_t h, l; split1(w, h, l);
        uint32_t off = sw_off(nn, k >> 3) + (k & 7) * 2;
        *(uint16_t*)(g_wbuf + GW_WOH + off) = h;
        *(uint16_t*)(g_wbuf + GW_WOL + off) = l;
    }
}

__global__ void __launch_bounds__(TPB, 2)
nerf_mma_kernel(const float* __restrict__ ox, const float* __restrict__ oy,
                const float* __restrict__ oz, const float* __restrict__ dxv,
                const float* __restrict__ dyv, const float* __restrict__ dzv,
                const float* __restrict__ tmin, const float* __restrict__ tmax,
                const float* __restrict__ b1, const float* __restrict__ b2,
                const float* __restrict__ bo,
                const float* __restrict__ Wrgb, const float* __restrict__ brgb,
                float* __restrict__ out, int n)
{
    extern __shared__ __align__(1024) char smem[];
    const uint32_t sb = smem_to_u32(smem);
    const int tid  = threadIdx.x;
    const int rayi = tid >> 7;
    const int rtid = tid & 127;
    const int lid  = tid & 31;
    const int wray = (tid >> 5) & 3;
    const int wbase = wray * 32;
    const uint32_t AH = SM_A + rayi * 32768;
    const uint32_t AL = AH + 16384;

    // ---- stage weights (vector copy of preconverted tiles) ----
    {
        const uint4* src = (const uint4*)g_wbuf;
        uint4* dst = (uint4*)(smem + SM_W);
        for (int i = tid; i < 2560; i += TPB) dst[i] = src[i];
        float* s = (float*)smem;
        for (int i = tid; i < 64; i += TPB) s[(SM_B1 >> 2) + i] = b1[i];
        for (int i = tid; i < 64; i += TPB) s[(SM_B2 >> 2) + i] = b2[i];
        for (int i = tid; i < 17; i += TPB) s[(SM_BO >> 2) + i] = bo[i];
        for (int i = tid; i < 48; i += TPB) s[(SM_WRGB >> 2) + i] = Wrgb[i];
        for (int i = tid; i < 3;  i += TPB) s[(SM_BRGB >> 2) + i] = brgb[i];
    }

    // ---- positional encodings -> A tile (row = sample = rtid) ----
    const int ray = blockIdx.x * RAYS_PER_CTA + rayi;
    const float tmn = tmin[ray], tmx = tmax[ray];
    const float t  = fmaf((float)rtid * (1.0f / (float)(SS - 1)), tmx - tmn, tmn);
    {
        float e[64];
        e[0] = fmaf(dxv[ray], t, ox[ray]);
        e[1] = fmaf(dyv[ray], t, oy[ray]);
        e[2] = fmaf(dzv[ray], t, oz[ray]);
        e[63] = 0.f;
#pragma unroll 1
        for (int c = 0; c < 3; c++) {
            float sv, cv;
            __sincosf(e[c], &sv, &cv);
#pragma unroll
            for (int f = 0; f < LFREQ; f++) {
                e[3 + 20 * c + f]      = sv;
                e[3 + 20 * c + 10 + f] = cv;
                float ns = 2.0f * sv * cv;
                float nc = fmaf(cv, cv, -(sv * sv));
                sv = ns; cv = nc;
            }
        }
        uint32_t hi[32], lo[32];
#pragma unroll
        for (int j = 0; j < 32; j++) split2(e[2 * j], e[2 * j + 1], hi[j], lo[j]);
#pragma unroll
        for (int q = 0; q < 8; q++) {
            uint32_t off = sw_off(rtid, q);
            *(uint4*)(smem + AH + off) = make_uint4(hi[4*q], hi[4*q+1], hi[4*q+2], hi[4*q+3]);
            *(uint4*)(smem + AL + off) = make_uint4(lo[4*q], lo[4*q+1], lo[4*q+2], lo[4*q+3]);
        }
    }
    __syncthreads();

    // lane-derived ldmatrix coordinates
    const int lj = lid >> 3, lr = lid & 7;
    const int a_rl  = ((lj & 1) << 3) + lr;
    const int a_c4h = lj >> 1;
    const int b_nl  = ((lj >> 1) << 3) + lr;
    const int b_c4h = lj & 1;
    const int c2l   = 2 * (lid & 3);

    float acc[2][8][4];
    uint32_t ahr[2][4][4], alr[2][4][4];   // register A fragments (hi/lo)

    // ================= layer 1 (A from smem) =================
#pragma unroll
    for (int mt = 0; mt < 2; mt++)
#pragma unroll
        for (int j = 0; j < 8; j++)
#pragma unroll
            for (int v = 0; v < 4; v++) acc[mt][j][v] = 0.f;

#pragma unroll
    for (int ks = 0; ks < 4; ks++) {
        uint32_t ahs[2][4], als[2][4];
#pragma unroll
        for (int mt = 0; mt < 2; mt++) {
            uint32_t off = sw_off(wbase + mt * 16 + a_rl, ks * 2 + a_c4h);
            ldsm4(ahs[mt], sb + AH + off);
            ldsm4(als[mt], sb + AL + off);
        }
#pragma unroll
        for (int p = 0; p < 4; p++) {
            uint32_t wh[4], wl[4];
            uint32_t off = sw_off(p * 16 + b_nl, ks * 2 + b_c4h);
            ldsm4(wh, sb + SM_W1H + off);
            ldsm4(wl, sb + SM_W1L + off);
#pragma unroll
            for (int mt = 0; mt < 2; mt++) {
                mma16816(acc[mt][2*p],   ahs[mt], wh[0], wh[1]);
                mma16816(acc[mt][2*p],   ahs[mt], wl[0], wl[1]);
                mma16816(acc[mt][2*p],   als[mt], wh[0], wh[1]);
                mma16816(acc[mt][2*p+1], ahs[mt], wh[2], wh[3]);
                mma16816(acc[mt][2*p+1], ahs[mt], wl[2], wl[3]);
                mma16816(acc[mt][2*p+1], als[mt], wh[2], wh[3]);
            }
        }
    }

    // epilogue 1: bias+relu+split -> register A fragments
    {
        const float* bias = (const float*)(smem + SM_B1);
#pragma unroll
        for (int mt = 0; mt < 2; mt++)
#pragma unroll
            for (int j = 0; j < 8; j++) {
                int cb = 8 * j + c2l;
                float v0 = fmaxf(acc[mt][j][0] + bias[cb],     0.f);
                float v1 = fmaxf(acc[mt][j][1] + bias[cb + 1], 0.f);
                float v2 = fmaxf(acc[mt][j][2] + bias[cb],     0.f);
                float v3 = fmaxf(acc[mt][j][3] + bias[cb + 1], 0.f);
                uint32_t h01, l01, h23, l23;
                split2(v0, v1, h01, l01);
                split2(v2, v3, h23, l23);
                int s = j >> 1, hf = j & 1;
                ahr[mt][s][2*hf]   = h01; ahr[mt][s][2*hf+1] = h23;
                alr[mt][s][2*hf]   = l01; alr[mt][s][2*hf+1] = l23;
            }
    }

    // ================= layer 2 (A from registers) =================
#pragma unroll
    for (int mt = 0; mt < 2; mt++)
#pragma unroll
        for (int j = 0; j < 8; j++)
#pragma unroll
            for (int v = 0; v < 4; v++) acc[mt][j][v] = 0.f;

#pragma unroll
    for (int ks = 0; ks < 4; ks++) {
#pragma unroll
        for (int p = 0; p < 4; p++) {
            uint32_t wh[4], wl[4];
            uint32_t off = sw_off(p * 16 + b_nl, ks * 2 + b_c4h);
            ldsm4(wh, sb + SM_W2H + off);
            ldsm4(wl, sb + SM_W2L + off);
#pragma unroll
            for (int mt = 0; mt < 2; mt++) {
                mma16816(acc[mt][2*p],   ahr[mt][ks], wh[0], wh[1]);
                mma16816(acc[mt][2*p],   ahr[mt][ks], wl[0], wl[1]);
                mma16816(acc[mt][2*p],   alr[mt][ks], wh[0], wh[1]);
                mma16816(acc[mt][2*p+1], ahr[mt][ks], wh[2], wh[3]);
                mma16816(acc[mt][2*p+1], ahr[mt][ks], wl[2], wl[3]);
                mma16816(acc[mt][2*p+1], alr[mt][ks], wh[2], wh[3]);
            }
        }
    }

    // epilogue 2 -> overwrite register A fragments
    {
        const float* bias = (const float*)(smem + SM_B2);
#pragma unroll
        for (int mt = 0; mt < 2; mt++)
#pragma unroll
            for (int j = 0; j < 8; j++) {
                int cb = 8 * j + c2l;
                float v0 = fmaxf(acc[mt][j][0] + bias[cb],     0.f);
                float v1 = fmaxf(acc[mt][j][1] + bias[cb + 1], 0.f);
                float v2 = fmaxf(acc[mt][j][2] + bias[cb],     0.f);
                float v3 = fmaxf(acc[mt][j][3] + bias[cb + 1], 0.f);
                uint32_t h01, l01, h23, l23;
                split2(v0, v1, h01, l01);
                split2(v2, v3, h23, l23);
                int s = j >> 1, hf = j & 1;
                ahr[mt][s][2*hf]   = h01; ahr[mt][s][2*hf+1] = h23;
                alr[mt][s][2*hf]   = l01; alr[mt][s][2*hf+1] = l23;
            }
    }

    // ================= layer 3 (3 n-tiles: cols 0..23, 17 valid) =================
#pragma unroll
    for (int mt = 0; mt < 2; mt++)
#pragma unroll
        for (int j = 0; j < 3; j++)
#pragma unroll
            for (int v = 0; v < 4; v++) acc[mt][j][v] = 0.f;

#pragma unroll
    for (int ks = 0; ks < 4; ks++) {
#pragma unroll
        for (int p = 0; p < 2; p++) {
            uint32_t wh[4], wl[4];
            uint32_t off = sw_off(p * 16 + b_nl, ks * 2 + b_c4h);
            ldsm4(wh, sb + SM_WOH + off);
            ldsm4(wl, sb + SM_WOL + off);
#pragma unroll
            for (int mt = 0; mt < 2; mt++) {
                mma16816(acc[mt][2*p],   ahr[mt][ks], wh[0], wh[1]);
                mma16816(acc[mt][2*p],   ahr[mt][ks], wl[0], wl[1]);
                mma16816(acc[mt][2*p],   alr[mt][ks], wh[0], wh[1]);
                if (p == 0) {
                    mma16816(acc[mt][1], ahr[mt][ks], wh[2], wh[3]);
                    mma16816(acc[mt][1], ahr[mt][ks], wl[2], wl[3]);
                    mma16816(acc[mt][1], alr[mt][ks], wh[2], wh[3]);
                }
            }
        }
    }

    // A tiles dead (layers 2-3 ran from registers); alias OUT staging onto AH
    __syncthreads();
    {
        const float* bos = (const float*)(smem + SM_BO);
        float* po = (float*)(smem + AH);   // 128 rows x 20 f32
#pragma unroll
        for (int mt = 0; mt < 2; mt++)
#pragma unroll
            for (int j = 0; j < 3; j++) {
                int cb = 8 * j + c2l;
                if (cb <= 16) {
                    int r0 = wbase + mt * 16 + (lid >> 2);
                    float bv0 = bos[cb];
                    float bv1 = (cb + 1 < 17) ? bos[cb + 1] : 0.f;
                    po[r0 * 20 + cb]           = acc[mt][j][0] + bv0;
                    po[r0 * 20 + cb + 1]       = acc[mt][j][1] + bv1;
                    po[(r0 + 8) * 20 + cb]     = acc[mt][j][2] + bv0;
                    po[(r0 + 8) * 20 + cb + 1] = acc[mt][j][3] + bv1;
                }
            }
    }
    __syncthreads();

    // ---------------- per-sample tail ----------------
    {
        const float* myo = (const float*)(smem + AH) + rtid * 20;
        const float sigma = fmaxf(myo[0], 0.f);
        const float* wrgb = (const float*)(smem + SM_WRGB);
        const float* brg  = (const float*)(smem + SM_BRGB);
        float rgbv[3];
#pragma unroll
        for (int cc = 0; cc < 3; cc++) {
            float r = brg[cc];
#pragma unroll
            for (int k = 0; k < 16; k++) r = fmaf(myo[1 + k], wrgb[k * 3 + cc], r);
            rgbv[cc] = __fdividef(1.0f, 1.0f + __expf(-r));
        }

        const float dtv   = g_dt;
        const float alpha = 1.0f - __expf(-sigma * dtv);
        const float q     = (1.0f - alpha) + 1e-10f;

        float p = q;
#pragma unroll
        for (int d = 1; d < 32; d <<= 1) {
            float u = __shfl_up_sync(0xffffffffu, p, d);
            if (lid >= d) p *= u;
        }
        __shared__ float wtot[RAYS_PER_CTA][4];
        if (lid == 31) wtot[rayi][wray] = p;
        __syncthreads();
        float pre = 1.0f;
        for (int w = 0; w < wray; w++) pre *= wtot[rayi][w];
        float excl = __shfl_up_sync(0xffffffffu, p, 1);
        if (lid == 0) excl = 1.0f;
        const float T    = pre * excl;
        const float incl = pre * p;
        const float wgt  = (T > 1e-4f) ? (T * alpha) : 0.f;

        float v0 = wgt * rgbv[0], v1 = wgt * rgbv[1], v2 = wgt * rgbv[2];
#pragma unroll
        for (int off = 16; off > 0; off >>= 1) {
            v0 += __shfl_down_sync(0xffffffffu, v0, off);
            v1 += __shfl_down_sync(0xffffffffu, v1, off);
            v2 += __shfl_down_sync(0xffffffffu, v2, off);
        }
        __shared__ float redc[RAYS_PER_CTA][4][3];
        if (lid == 0) { redc[rayi][wray][0] = v0; redc[rayi][wray][1] = v1; redc[rayi][wray][2] = v2; }
        if (rtid == SS - 1) out[3 * n + ray] = incl;
        __syncthreads();
        if (rtid == 0) {
            out[ray * 3 + 0] = redc[rayi][0][0] + redc[rayi][1][0] + redc[rayi][2][0] + redc[rayi][3][0];
            out[ray * 3 + 1] = redc[rayi][0][1] + redc[rayi][1][1] + redc[rayi][2][1] + redc[rayi][3][1];
            out[ray * 3 + 2] = redc[rayi][0][2] + redc[rayi][1][2] + redc[rayi][2][2] + redc[rayi][3][2];
        }
    }
}

extern "C" void kernel_launch(void* const* d_in, const int* in_sizes, int n_in,
                              void* d_out, int out_size) {
    const float* ox   = (const float*)d_in[0];
    const float* oy   = (const float*)d_in[1];
    const float* oz   = (const float*)d_in[2];
    const float* dxv  = (const float*)d_in[3];
    const float* dyv  = (const float*)d_in[4];
    const float* dzv  = (const float*)d_in[5];
    const float* tmin = (const float*)d_in[6];
    const float* tmax = (const float*)d_in[7];
    const float* W1   = (const float*)d_in[8];
    const float* b1   = (const float*)d_in[9];
    const float* W2   = (const float*)d_in[10];
    const float* b2   = (const float*)d_in[11];
    const float* Wo   = (const float*)d_in[12];
    const float* bo   = (const float*)d_in[13];
    const float* Wrgb = (const float*)d_in[14];
    const float* brgb = (const float*)d_in[15];
    float* out = (float*)d_out;
    const int n = in_sizes[0];

    cudaFuncSetAttribute(nerf_mma_kernel, cudaFuncAttributeMaxDynamicSharedMemorySize, SM_TOTAL);

    prep_kernel<<<1, 256>>>(tmin, tmax, W1, W2, Wo, n);
    nerf_mma_kernel<<<n / RAYS_PER_CTA, TPB, SM_TOTAL>>>(
        ox, oy, oz, dxv, dyv, dzv, tmin, tmax,
        b1, b2, bo, Wrgb, brgb, out, n);
}

// round 10
// speedup vs baseline: 2.2998x; 1.1090x over previous
#include <cuda_runtime.h>
#include <cuda_bf16.h>
#include <cstdint>
#include <math.h>

#define SS    128
#define LFREQ 10

__device__ float g_dt;
__device__ __align__(16) unsigned char g_wbuf[40960];   // pre-swizzled bf16 hi/lo weights

#define GW_W1H 0
#define GW_W1L 8192
#define GW_W2H 16384
#define GW_W2L 24576
#define GW_WOH 32768
#define GW_WOL 36864

// ---------------- helpers ----------------
__device__ __forceinline__ uint32_t smem_to_u32(const void* p) {
    uint32_t a;
    asm("{ .reg .u64 t; cvta.to.shared.u64 t, %1; cvt.u32.u64 %0, t; }" : "=r"(a) : "l"(p));
    return a;
}

__device__ __forceinline__ void ldsm4(uint32_t* r, uint32_t addr) {
    asm volatile("ldmatrix.sync.aligned.m8n8.x4.shared.b16 {%0,%1,%2,%3}, [%4];"
        : "=r"(r[0]), "=r"(r[1]), "=r"(r[2]), "=r"(r[3]) : "r"(addr));
}

__device__ __forceinline__ void mma16816(float* d, const uint32_t* a, uint32_t b0, uint32_t b1) {
    asm volatile("mma.sync.aligned.m16n8k16.row.col.f32.bf16.bf16.f32 "
        "{%0,%1,%2,%3}, {%4,%5,%6,%7}, {%8,%9}, {%0,%1,%2,%3};"
        : "+f"(d[0]), "+f"(d[1]), "+f"(d[2]), "+f"(d[3])
        : "r"(a[0]), "r"(a[1]), "r"(a[2]), "r"(a[3]), "r"(b0), "r"(b1));
}

__device__ __forceinline__ void split1(float x, uint16_t& h, uint16_t& l) {
    uint16_t hb = __bfloat16_as_ushort(__float2bfloat16_rn(x));
    float r = __uint_as_float(((uint32_t)hb) << 16);
    uint16_t lb = __bfloat16_as_ushort(__float2bfloat16_rn(x - r));
    h = hb; l = lb;
}

// packed split: h = bf16x2(a,b), l = bf16x2 of residuals
__device__ __forceinline__ void split2(float a, float b, uint32_t& h, uint32_t& l) {
    uint32_t hh;
    asm("cvt.rn.bf16x2.f32 %0, %1, %2;" : "=r"(hh) : "f"(b), "f"(a));
    float ra = __uint_as_float(hh << 16);
    float rb = __uint_as_float(hh & 0xFFFF0000u);
    float da = a - ra, db = b - rb;
    uint32_t ll;
    asm("cvt.rn.bf16x2.f32 %0, %1, %2;" : "=r"(ll) : "f"(db), "f"(da));
    h = hh; l = ll;
}

// swizzled tile byte offset: row-major, 128B rows, 16B granules XORed
__device__ __forceinline__ uint32_t sw_off(int row, int c4) {
    return (uint32_t)(row * 128 + ((c4 ^ (row & 7)) << 4));
}

#define BARSYNC(id, cnt) asm volatile("bar.sync %0, %1;" :: "r"(id), "r"(cnt) : "memory")

// ---------------- SMEM layout (byte offsets) ----------------
#define SM_B1    0
#define SM_B2    256
#define SM_BO    512
#define SM_WRGB  640
#define SM_BRGB  832
#define SM_W     1024
#define SM_W1H   (SM_W + GW_W1H)
#define SM_W1L   (SM_W + GW_W1L)
#define SM_W2H   (SM_W + GW_W2H)
#define SM_W2L   (SM_W + GW_W2L)
#define SM_WOH   (SM_W + GW_WOH)
#define SM_WOL   (SM_W + GW_WOL)
#define SM_A     41984   // 1 ray: 16384 hi + 16384 lo
#define SM_TOTAL (41984 + 32768)   // 74752

#define TPB 256

// -------- prep: dt reduction + weight conversion (one CTA) --------
__global__ void prep_kernel(const float* __restrict__ tmin, const float* __restrict__ tmax,
                            const float* __restrict__ W1, const float* __restrict__ W2,
                            const float* __restrict__ Wo, int n) {
    __shared__ float red[256];
    int tid = threadIdx.x;
    float acc = 0.f;
    for (int i = tid; i < n; i += 256) acc += tmax[i] - tmin[i];
    red[tid] = acc;
    __syncthreads();
    for (int s = 128; s > 0; s >>= 1) {
        if (tid < s) red[tid] += red[tid + s];
        __syncthreads();
    }
    if (tid == 0) g_dt = (red[0] / (float)n) / (float)SS;

    for (int idx = tid; idx < 64 * 64; idx += 256) {
        int nn = idx >> 6, k = idx & 63;
        float w = (k < 63) ? W1[k * 64 + nn] : 0.f;
        uint16_t h, l; split1(w, h, l);
        uint32_t off = sw_off(nn, k >> 3) + (k & 7) * 2;
        *(uint16_t*)(g_wbuf + GW_W1H + off) = h;
        *(uint16_t*)(g_wbuf + GW_W1L + off) = l;
    }
    for (int idx = tid; idx < 64 * 64; idx += 256) {
        int nn = idx >> 6, k = idx & 63;
        float w = W2[k * 64 + nn];
        uint16_t h, l; split1(w, h, l);
        uint32_t off = sw_off(nn, k >> 3) + (k & 7) * 2;
        *(uint16_t*)(g_wbuf + GW_W2H + off) = h;
        *(uint16_t*)(g_wbuf + GW_W2L + off) = l;
    }
    for (int idx = tid; idx < 32 * 64; idx += 256) {
        int nn = idx >> 6, k = idx & 63;
        float w = (nn < 17) ? Wo[k * 17 + nn] : 0.f;
        uint16_t h, l; split1(w, h, l);
        uint32_t off = sw_off(nn, k >> 3) + (k & 7) * 2;
        *(uint16_t*)(g_wbuf + GW_WOH + off) = h;
        *(uint16_t*)(g_wbuf + GW_WOL + off) = l;
    }
}

__global__ void __launch_bounds__(TPB, 3)
nerf_mma_kernel(const float* __restrict__ ox, const float* __restrict__ oy,
                const float* __restrict__ oz, const float* __restrict__ dxv,
                const float* __restrict__ dyv, const float* __restrict__ dzv,
                const float* __restrict__ tmin, const float* __restrict__ tmax,
                const float* __restrict__ b1, const float* __restrict__ b2,
                const float* __restrict__ bo,
                const float* __restrict__ Wrgb, const float* __restrict__ brgb,
                float* __restrict__ out, int n)
{
    extern __shared__ __align__(1024) char smem[];
    const uint32_t sb = smem_to_u32(smem);
    const int tid  = threadIdx.x;
    const int lid  = tid & 31;
    const int wid  = tid >> 5;            // 0..7
    const int wbase = wid * 16;           // 16 rows per warp
    const uint32_t AH = SM_A;
    const uint32_t AL = AH + 16384;
    const int ray = blockIdx.x;

    // ---- stage weights (vector copy of preconverted tiles) ----
    {
        const uint4* src = (const uint4*)g_wbuf;
        uint4* dst = (uint4*)(smem + SM_W);
        for (int i = tid; i < 2560; i += TPB) dst[i] = src[i];
        float* s = (float*)smem;
        for (int i = tid; i < 64; i += TPB) s[(SM_B1 >> 2) + i] = b1[i];
        for (int i = tid; i < 64; i += TPB) s[(SM_B2 >> 2) + i] = b2[i];
        for (int i = tid; i < 17; i += TPB) s[(SM_BO >> 2) + i] = bo[i];
        for (int i = tid; i < 48; i += TPB) s[(SM_WRGB >> 2) + i] = Wrgb[i];
        for (int i = tid; i < 3;  i += TPB) s[(SM_BRGB >> 2) + i] = brgb[i];
    }

    // ---- positional encodings -> A tile (threads 0..127, row = tid) ----
    if (tid < SS) {
        const float tmn = tmin[ray], tmx = tmax[ray];
        const float t  = fmaf((float)tid * (1.0f / (float)(SS - 1)), tmx - tmn, tmn);
        float e[64];
        e[0] = fmaf(dxv[ray], t, ox[ray]);
        e[1] = fmaf(dyv[ray], t, oy[ray]);
        e[2] = fmaf(dzv[ray], t, oz[ray]);
        e[63] = 0.f;
#pragma unroll 1
        for (int c = 0; c < 3; c++) {
            float sv, cv;
            __sincosf(e[c], &sv, &cv);
#pragma unroll
            for (int f = 0; f < LFREQ; f++) {
                e[3 + 20 * c + f]      = sv;
                e[3 + 20 * c + 10 + f] = cv;
                float ns = 2.0f * sv * cv;
                float nc = fmaf(cv, cv, -(sv * sv));
                sv = ns; cv = nc;
            }
        }
        uint32_t hi[32], lo[32];
#pragma unroll
        for (int j = 0; j < 32; j++) split2(e[2 * j], e[2 * j + 1], hi[j], lo[j]);
#pragma unroll
        for (int q = 0; q < 8; q++) {
            uint32_t off = sw_off(tid, q);
            *(uint4*)(smem + AH + off) = make_uint4(hi[4*q], hi[4*q+1], hi[4*q+2], hi[4*q+3]);
            *(uint4*)(smem + AL + off) = make_uint4(lo[4*q], lo[4*q+1], lo[4*q+2], lo[4*q+3]);
        }
    }
    __syncthreads();

    // lane-derived ldmatrix coordinates
    const int lj = lid >> 3, lr = lid & 7;
    const int a_rl  = ((lj & 1) << 3) + lr;
    const int a_c4h = lj >> 1;
    const int b_nl  = ((lj >> 1) << 3) + lr;
    const int b_c4h = lj & 1;
    const int c2l   = 2 * (lid & 3);

    float acc[8][4];
    uint32_t ahr[4][4], alr[4][4];   // register A fragments (hi/lo)

    // ================= layer 1 (A from smem, 16 rows/warp) =================
#pragma unroll
    for (int j = 0; j < 8; j++)
#pragma unroll
        for (int v = 0; v < 4; v++) acc[j][v] = 0.f;

#pragma unroll
    for (int ks = 0; ks < 4; ks++) {
        uint32_t ahs[4], als[4];
        {
            uint32_t off = sw_off(wbase + a_rl, ks * 2 + a_c4h);
            ldsm4(ahs, sb + AH + off);
            ldsm4(als, sb + AL + off);
        }
#pragma unroll
        for (int p = 0; p < 4; p++) {
            uint32_t wh[4], wl[4];
            uint32_t off = sw_off(p * 16 + b_nl, ks * 2 + b_c4h);
            ldsm4(wh, sb + SM_W1H + off);
            ldsm4(wl, sb + SM_W1L + off);
            mma16816(acc[2*p],   ahs, wh[0], wh[1]);
            mma16816(acc[2*p],   ahs, wl[0], wl[1]);
            mma16816(acc[2*p],   als, wh[0], wh[1]);
            mma16816(acc[2*p+1], ahs, wh[2], wh[3]);
            mma16816(acc[2*p+1], ahs, wl[2], wl[3]);
            mma16816(acc[2*p+1], als, wh[2], wh[3]);
        }
    }

    // epilogue 1: bias+relu+split -> register A fragments
    {
        const float* bias = (const float*)(smem + SM_B1);
#pragma unroll
        for (int j = 0; j < 8; j++) {
            int cb = 8 * j + c2l;
            float v0 = fmaxf(acc[j][0] + bias[cb],     0.f);
            float v1 = fmaxf(acc[j][1] + bias[cb + 1], 0.f);
            float v2 = fmaxf(acc[j][2] + bias[cb],     0.f);
            float v3 = fmaxf(acc[j][3] + bias[cb + 1], 0.f);
            uint32_t h01, l01, h23, l23;
            split2(v0, v1, h01, l01);
            split2(v2, v3, h23, l23);
            int s = j >> 1, hf = j & 1;
            ahr[s][2*hf]   = h01; ahr[s][2*hf+1] = h23;
            alr[s][2*hf]   = l01; alr[s][2*hf+1] = l23;
        }
    }

    // ================= layer 2 (A from registers) =================
#pragma unroll
    for (int j = 0; j < 8; j++)
#pragma unroll
        for (int v = 0; v < 4; v++) acc[j][v] = 0.f;

#pragma unroll
    for (int ks = 0; ks < 4; ks++) {
#pragma unroll
        for (int p = 0; p < 4; p++) {
            uint32_t wh[4], wl[4];
            uint32_t off = sw_off(p * 16 + b_nl, ks * 2 + b_c4h);
            ldsm4(wh, sb + SM_W2H + off);
            ldsm4(wl, sb + SM_W2L + off);
            mma16816(acc[2*p],   ahr[ks], wh[0], wh[1]);
            mma16816(acc[2*p],   ahr[ks], wl[0], wl[1]);
            mma16816(acc[2*p],   alr[ks], wh[0], wh[1]);
            mma16816(acc[2*p+1], ahr[ks], wh[2], wh[3]);
            mma16816(acc[2*p+1], ahr[ks], wl[2], wl[3]);
            mma16816(acc[2*p+1], alr[ks], wh[2], wh[3]);
        }
    }

    // epilogue 2 -> overwrite register A fragments
    {
        const float* bias = (const float*)(smem + SM_B2);
#pragma unroll
        for (int j = 0; j < 8; j++) {
            int cb = 8 * j + c2l;
            float v0 = fmaxf(acc[j][0] + bias[cb],     0.f);
            float v1 = fmaxf(acc[j][1] + bias[cb + 1], 0.f);
            float v2 = fmaxf(acc[j][2] + bias[cb],     0.f);
            float v3 = fmaxf(acc[j][3] + bias[cb + 1], 0.f);
            uint32_t h01, l01, h23, l23;
            split2(v0, v1, h01, l01);
            split2(v2, v3, h23, l23);
            int s = j >> 1, hf = j & 1;
            ahr[s][2*hf]   = h01; ahr[s][2*hf+1] = h23;
            alr[s][2*hf]   = l01; alr[s][2*hf+1] = l23;
        }
    }

    // ================= layer 3 (3 n-tiles: cols 0..23, 17 valid) =================
#pragma unroll
    for (int j = 0; j < 3; j++)
#pragma unroll
        for (int v = 0; v < 4; v++) acc[j][v] = 0.f;

#pragma unroll
    for (int ks = 0; ks < 4; ks++) {
#pragma unroll
        for (int p = 0; p < 2; p++) {
            uint32_t wh[4], wl[4];
            uint32_t off = sw_off(p * 16 + b_nl, ks * 2 + b_c4h);
            ldsm4(wh, sb + SM_WOH + off);
            ldsm4(wl, sb + SM_WOL + off);
            mma16816(acc[2*p],   ahr[ks], wh[0], wh[1]);
            mma16816(acc[2*p],   ahr[ks], wl[0], wl[1]);
            mma16816(acc[2*p],   alr[ks], wh[0], wh[1]);
            if (p == 0) {
                mma16816(acc[1], ahr[ks], wh[2], wh[3]);
                mma16816(acc[1], ahr[ks], wl[2], wl[3]);
                mma16816(acc[1], alr[ks], wh[2], wh[3]);
            }
        }
    }

    // A tile dead (layers 2-3 ran from registers); alias OUT staging onto AH
    __syncthreads();
    {
        const float* bos = (const float*)(smem + SM_BO);
        float* po = (float*)(smem + AH);   // 128 rows x 20 f32 = 10240B
#pragma unroll
        for (int j = 0; j < 3; j++) {
            int cb = 8 * j + c2l;
            if (cb <= 16) {
                int r0 = wbase + (lid >> 2);
                float bv0 = bos[cb];
                float bv1 = (cb + 1 < 17) ? bos[cb + 1] : 0.f;
                po[r0 * 20 + cb]           = acc[j][0] + bv0;
                po[r0 * 20 + cb + 1]       = acc[j][1] + bv1;
                po[(r0 + 8) * 20 + cb]     = acc[j][2] + bv0;
                po[(r0 + 8) * 20 + cb + 1] = acc[j][3] + bv1;
            }
        }
    }
    __syncthreads();

    // ---------------- per-sample tail (threads 0..127) ----------------
    if (tid < SS) {
        const int wray = tid >> 5;   // 0..3
        const float* myo = (const float*)(smem + AH) + tid * 20;
        const float sigma = fmaxf(myo[0], 0.f);
        const float* wrgb = (const float*)(smem + SM_WRGB);
        const float* brg  = (const float*)(smem + SM_BRGB);
        float rgbv[3];
#pragma unroll
        for (int cc = 0; cc < 3; cc++) {
            float r = brg[cc];
#pragma unroll
            for (int k = 0; k < 16; k++) r = fmaf(myo[1 + k], wrgb[k * 3 + cc], r);
            rgbv[cc] = __fdividef(1.0f, 1.0f + __expf(-r));
        }

        const float dtv   = g_dt;
        const float alpha = 1.0f - __expf(-sigma * dtv);
        const float q     = (1.0f - alpha) + 1e-10f;

        float p = q;
#pragma unroll
        for (int d = 1; d < 32; d <<= 1) {
            float u = __shfl_up_sync(0xffffffffu, p, d);
            if (lid >= d) p *= u;
        }
        __shared__ float wtot[4];
        if (lid == 31) wtot[wray] = p;
        BARSYNC(1, 128);
        float pre = 1.0f;
        for (int w = 0; w < wray; w++) pre *= wtot[w];
        float excl = __shfl_up_sync(0xffffffffu, p, 1);
        if (lid == 0) excl = 1.0f;
        const float T    = pre * excl;
        const float incl = pre * p;
        const float wgt  = (T > 1e-4f) ? (T * alpha) : 0.f;

        float v0 = wgt * rgbv[0], v1 = wgt * rgbv[1], v2 = wgt * rgbv[2];
#pragma unroll
        for (int off = 16; off > 0; off >>= 1) {
            v0 += __shfl_down_sync(0xffffffffu, v0, off);
            v1 += __shfl_down_sync(0xffffffffu, v1, off);
            v2 += __shfl_down_sync(0xffffffffu, v2, off);
        }
        __shared__ float redc[4][3];
        if (lid == 0) { redc[wray][0] = v0; redc[wray][1] = v1; redc[wray][2] = v2; }
        if (tid == SS - 1) out[3 * n + ray] = incl;
        BARSYNC(1, 128);
        if (tid == 0) {
            out[ray * 3 + 0] = redc[0][0] + redc[1][0] + redc[2][0] + redc[3][0];
            out[ray * 3 + 1] = redc[0][1] + redc[1][1] + redc[2][1] + redc[3][1];
            out[ray * 3 + 2] = redc[0][2] + redc[1][2] + redc[2][2] + redc[3][2];
        }
    }
}

extern "C" void kernel_launch(void* const* d_in, const int* in_sizes, int n_in,
                              void* d_out, int out_size) {
    const float* ox   = (const float*)d_in[0];
    const float* oy   = (const float*)d_in[1];
    const float* oz   = (const float*)d_in[2];
    const float* dxv  = (const float*)d_in[3];
    const float* dyv  = (const float*)d_in[4];
    const float* dzv  = (const float*)d_in[5];
    const float* tmin = (const float*)d_in[6];
    const float* tmax = (const float*)d_in[7];
    const float* W1   = (const float*)d_in[8];
    const float* b1   = (const float*)d_in[9];
    const float* W2   = (const float*)d_in[10];
    const float* b2   = (const float*)d_in[11];
    const float* Wo   = (const float*)d_in[12];
    const float* bo   = (const float*)d_in[13];
    const float* Wrgb = (const float*)d_in[14];
    const float* brgb = (const float*)d_in[15];
    float* out = (float*)d_out;
    const int n = in_sizes[0];

    cudaFuncSetAttribute(nerf_mma_kernel, cudaFuncAttributeMaxDynamicSharedMemorySize, SM_TOTAL);

    prep_kernel<<<1, 256>>>(tmin, tmax, W1, W2, Wo, n);
    nerf_mma_kernel<<<n, TPB, SM_TOTAL>>>(
        ox, oy, oz, dxv, dyv, dzv, tmin, tmax,
        b1, b2, bo, Wrgb, brgb, out, n);
}

// round 12
// speedup vs baseline: 3.0697x; 1.3348x over previous
#include <cuda_runtime.h>
#include <cuda_fp16.h>
#include <cstdint>
#include <math.h>

#define SS    128
#define LFREQ 10

__device__ float g_dt;
__device__ __align__(16) unsigned char g_wbuf[20480];   // pre-swizzled fp16 weights

#define GW_W1 0
#define GW_W2 8192
#define GW_WO 16384

// ---------------- helpers ----------------
__device__ __forceinline__ uint32_t smem_to_u32(const void* p) {
    uint32_t a;
    asm("{ .reg .u64 t; cvta.to.shared.u64 t, %1; cvt.u32.u64 %0, t; }" : "=r"(a) : "l"(p));
    return a;
}

__device__ __forceinline__ void ldsm4(uint32_t* r, uint32_t addr) {
    asm volatile("ldmatrix.sync.aligned.m8n8.x4.shared.b16 {%0,%1,%2,%3}, [%4];"
        : "=r"(r[0]), "=r"(r[1]), "=r"(r[2]), "=r"(r[3]) : "r"(addr));
}

__device__ __forceinline__ void mma16816(float* d, const uint32_t* a, uint32_t b0, uint32_t b1) {
    asm volatile("mma.sync.aligned.m16n8k16.row.col.f32.f16.f16.f32 "
        "{%0,%1,%2,%3}, {%4,%5,%6,%7}, {%8,%9}, {%0,%1,%2,%3};"
        : "+f"(d[0]), "+f"(d[1]), "+f"(d[2]), "+f"(d[3])
        : "r"(a[0]), "r"(a[1]), "r"(a[2]), "r"(a[3]), "r"(b0), "r"(b1));
}

// fp16 split of packed pair: h = half2(a,b), l = half2 of residuals (A exact to 2^-22)
__device__ __forceinline__ void split2h(float a, float b, uint32_t& h, uint32_t& l) {
    __half2 hh = __floats2half2_rn(a, b);
    h = *reinterpret_cast<uint32_t*>(&hh);
    float ra = __half2float(__low2half(hh));
    float rb = __half2float(__high2half(hh));
    __half2 ll = __floats2half2_rn(a - ra, b - rb);
    l = *reinterpret_cast<uint32_t*>(&ll);
}

// swizzled tile byte offset: row-major, 128B rows, 16B granules XORed
__device__ __forceinline__ uint32_t sw_off(int row, int c4) {
    return (uint32_t)(row * 128 + ((c4 ^ (row & 7)) << 4));
}

#define BARSYNC(id, cnt) asm volatile("bar.sync %0, %1;" :: "r"(id), "r"(cnt) : "memory")

// ---------------- SMEM layout (byte offsets) ----------------
#define SM_B1    0
#define SM_B2    256
#define SM_BO    512
#define SM_WRGB  640
#define SM_BRGB  832
#define SM_W     1024
#define SM_W1    (SM_W + GW_W1)
#define SM_W2    (SM_W + GW_W2)
#define SM_WO    (SM_W + GW_WO)
#define SM_A     21504   // 16384 hi + 16384 lo
#define SM_TOTAL (21504 + 32768)   // 54272

#define TPB 256

// -------- prep: dt reduction + weight conversion (one CTA) --------
__global__ void prep_kernel(const float* __restrict__ tmin, const float* __restrict__ tmax,
                            const float* __restrict__ W1, const float* __restrict__ W2,
                            const float* __restrict__ Wo, int n) {
    __shared__ float red[256];
    int tid = threadIdx.x;
    float acc = 0.f;
    for (int i = tid; i < n; i += 256) acc += tmax[i] - tmin[i];
    red[tid] = acc;
    __syncthreads();
    for (int s = 128; s > 0; s >>= 1) {
        if (tid < s) red[tid] += red[tid + s];
        __syncthreads();
    }
    if (tid == 0) g_dt = (red[0] / (float)n) / (float)SS;

    for (int idx = tid; idx < 64 * 64; idx += 256) {
        int nn = idx >> 6, k = idx & 63;
        float w = (k < 63) ? W1[k * 64 + nn] : 0.f;
        __half h = __float2half_rn(w);
        uint32_t off = sw_off(nn, k >> 3) + (k & 7) * 2;
        *(uint16_t*)(g_wbuf + GW_W1 + off) = *reinterpret_cast<uint16_t*>(&h);
    }
    for (int idx = tid; idx < 64 * 64; idx += 256) {
        int nn = idx >> 6, k = idx & 63;
        float w = W2[k * 64 + nn];
        __half h = __float2half_rn(w);
        uint32_t off = sw_off(nn, k >> 3) + (k & 7) * 2;
        *(uint16_t*)(g_wbuf + GW_W2 + off) = *reinterpret_cast<uint16_t*>(&h);
    }
    for (int idx = tid; idx < 32 * 64; idx += 256) {
        int nn = idx >> 6, k = idx & 63;
        float w = (nn < 17) ? Wo[k * 17 + nn] : 0.f;
        __half h = __float2half_rn(w);
        uint32_t off = sw_off(nn, k >> 3) + (k & 7) * 2;
        *(uint16_t*)(g_wbuf + GW_WO + off) = *reinterpret_cast<uint16_t*>(&h);
    }
}

__global__ void __launch_bounds__(TPB, 3)
nerf_mma_kernel(const float* __restrict__ ox, const float* __restrict__ oy,
                const float* __restrict__ oz, const float* __restrict__ dxv,
                const float* __restrict__ dyv, const float* __restrict__ dzv,
                const float* __restrict__ tmin, const float* __restrict__ tmax,
                const float* __restrict__ b1, const float* __restrict__ b2,
                const float* __restrict__ bo,
                const float* __restrict__ Wrgb, const float* __restrict__ brgb,
                float* __restrict__ out, int n)
{
    extern __shared__ __align__(1024) char smem[];
    const uint32_t sb = smem_to_u32(smem);
    const int tid  = threadIdx.x;
    const int lid  = tid & 31;
    const int wid  = tid >> 5;            // 0..7
    const int wbase = wid * 16;           // 16 rows per warp
    const uint32_t AH = SM_A;
    const uint32_t AL = AH + 16384;
    const int ray = blockIdx.x;

    // ---- stage weights (vector copy of preconverted fp16 tiles) ----
    {
        const uint4* src = (const uint4*)g_wbuf;
        uint4* dst = (uint4*)(smem + SM_W);
        for (int i = tid; i < 1280; i += TPB) dst[i] = src[i];
        float* s = (float*)smem;
        for (int i = tid; i < 64; i += TPB) s[(SM_B1 >> 2) + i] = b1[i];
        for (int i = tid; i < 64; i += TPB) s[(SM_B2 >> 2) + i] = b2[i];
        for (int i = tid; i < 17; i += TPB) s[(SM_BO >> 2) + i] = bo[i];
        for (int i = tid; i < 48; i += TPB) s[(SM_WRGB >> 2) + i] = Wrgb[i];
        for (int i = tid; i < 3;  i += TPB) s[(SM_BRGB >> 2) + i] = brgb[i];
    }

    // ---- positional encodings -> A tile (threads 0..127, row = tid) ----
    if (tid < SS) {
        const float tmn = tmin[ray], tmx = tmax[ray];
        const float t  = fmaf((float)tid * (1.0f / (float)(SS - 1)), tmx - tmn, tmn);
        float e[64];
        e[0] = fmaf(dxv[ray], t, ox[ray]);
        e[1] = fmaf(dyv[ray], t, oy[ray]);
        e[2] = fmaf(dzv[ray], t, oz[ray]);
        e[63] = 0.f;
#pragma unroll 1
        for (int c = 0; c < 3; c++) {
            float sv, cv;
            __sincosf(e[c], &sv, &cv);
#pragma unroll
            for (int f = 0; f < LFREQ; f++) {
                e[3 + 20 * c + f]      = sv;
                e[3 + 20 * c + 10 + f] = cv;
                float ns = 2.0f * sv * cv;
                float nc = fmaf(cv, cv, -(sv * sv));
                sv = ns; cv = nc;
            }
        }
        uint32_t hi[32], lo[32];
#pragma unroll
        for (int j = 0; j < 32; j++) split2h(e[2 * j], e[2 * j + 1], hi[j], lo[j]);
#pragma unroll
        for (int q = 0; q < 8; q++) {
            uint32_t off = sw_off(tid, q);
            *(uint4*)(smem + AH + off) = make_uint4(hi[4*q], hi[4*q+1], hi[4*q+2], hi[4*q+3]);
            *(uint4*)(smem + AL + off) = make_uint4(lo[4*q], lo[4*q+1], lo[4*q+2], lo[4*q+3]);
        }
    }
    __syncthreads();

    // lane-derived ldmatrix coordinates
    const int lj = lid >> 3, lr = lid & 7;
    const int a_rl  = ((lj & 1) << 3) + lr;
    const int a_c4h = lj >> 1;
    const int b_nl  = ((lj >> 1) << 3) + lr;
    const int b_c4h = lj & 1;
    const int c2l   = 2 * (lid & 3);

    float acc[8][4];
    uint32_t ahr[4][4], alr[4][4];   // register A fragments (hi/lo)

    // ================= layer 1 (A from smem, 16 rows/warp) =================
#pragma unroll
    for (int j = 0; j < 8; j++)
#pragma unroll
        for (int v = 0; v < 4; v++) acc[j][v] = 0.f;

#pragma unroll
    for (int ks = 0; ks < 4; ks++) {
        uint32_t ahs[4], als[4];
        {
            uint32_t off = sw_off(wbase + a_rl, ks * 2 + a_c4h);
            ldsm4(ahs, sb + AH + off);
            ldsm4(als, sb + AL + off);
        }
#pragma unroll
        for (int p = 0; p < 4; p++) {
            uint32_t wh[4];
            uint32_t off = sw_off(p * 16 + b_nl, ks * 2 + b_c4h);
            ldsm4(wh, sb + SM_W1 + off);
            mma16816(acc[2*p],   ahs, wh[0], wh[1]);
            mma16816(acc[2*p],   als, wh[0], wh[1]);
            mma16816(acc[2*p+1], ahs, wh[2], wh[3]);
            mma16816(acc[2*p+1], als, wh[2], wh[3]);
        }
    }

    // epilogue 1: bias+relu+split -> register A fragments
    {
        const float* bias = (const float*)(smem + SM_B1);
#pragma unroll
        for (int j = 0; j < 8; j++) {
            int cb = 8 * j + c2l;
            float v0 = fmaxf(acc[j][0] + bias[cb],     0.f);
            float v1 = fmaxf(acc[j][1] + bias[cb + 1], 0.f);
            float v2 = fmaxf(acc[j][2] + bias[cb],     0.f);
            float v3 = fmaxf(acc[j][3] + bias[cb + 1], 0.f);
            uint32_t h01, l01, h23, l23;
            split2h(v0, v1, h01, l01);
            split2h(v2, v3, h23, l23);
            int s = j >> 1, hf = j & 1;
            ahr[s][2*hf]   = h01; ahr[s][2*hf+1] = h23;
            alr[s][2*hf]   = l01; alr[s][2*hf+1] = l23;
        }
    }

    // ================= layer 2 (A from registers) =================
#pragma unroll
    for (int j = 0; j < 8; j++)
#pragma unroll
        for (int v = 0; v < 4; v++) acc[j][v] = 0.f;

#pragma unroll
    for (int ks = 0; ks < 4; ks++) {
#pragma unroll
        for (int p = 0; p < 4; p++) {
            uint32_t wh[4];
            uint32_t off = sw_off(p * 16 + b_nl, ks * 2 + b_c4h);
            ldsm4(wh, sb + SM_W2 + off);
            mma16816(acc[2*p],   ahr[ks], wh[0], wh[1]);
            mma16816(acc[2*p],   alr[ks], wh[0], wh[1]);
            mma16816(acc[2*p+1], ahr[ks], wh[2], wh[3]);
            mma16816(acc[2*p+1], alr[ks], wh[2], wh[3]);
        }
    }

    // epilogue 2 -> overwrite register A fragments
    {
        const float* bias = (const float*)(smem + SM_B2);
#pragma unroll
        for (int j = 0; j < 8; j++) {
            int cb = 8 * j + c2l;
            float v0 = fmaxf(acc[j][0] + bias[cb],     0.f);
            float v1 = fmaxf(acc[j][1] + bias[cb + 1], 0.f);
            float v2 = fmaxf(acc[j][2] + bias[cb],     0.f);
            float v3 = fmaxf(acc[j][3] + bias[cb + 1], 0.f);
            uint32_t h01, l01, h23, l23;
            split2h(v0, v1, h01, l01);
            split2h(v2, v3, h23, l23);
            int s = j >> 1, hf = j & 1;
            ahr[s][2*hf]   = h01; ahr[s][2*hf+1] = h23;
            alr[s][2*hf]   = l01; alr[s][2*hf+1] = l23;
        }
    }

    // ================= layer 3 (3 n-tiles: cols 0..23, 17 valid) =================
#pragma unroll
    for (int j = 0; j < 3; j++)
#pragma unroll
        for (int v = 0; v < 4; v++) acc[j][v] = 0.f;

#pragma unroll
    for (int ks = 0; ks < 4; ks++) {
#pragma unroll
        for (int p = 0; p < 2; p++) {
            uint32_t wh[4];
            uint32_t off = sw_off(p * 16 + b_nl, ks * 2 + b_c4h);
            ldsm4(wh, sb + SM_WO + off);
            mma16816(acc[2*p],   ahr[ks], wh[0], wh[1]);
            mma16816(acc[2*p],   alr[ks], wh[0], wh[1]);
            if (p == 0) {
                mma16816(acc[1], ahr[ks], wh[2], wh[3]);
                mma16816(acc[1], alr[ks], wh[2], wh[3]);
            }
        }
    }

    // A tile dead (layers 2-3 ran from registers); alias OUT staging onto AH
    __syncthreads();
    {
        const float* bos = (const float*)(smem + SM_BO);
        float* po = (float*)(smem + AH);   // 128 rows x 20 f32 = 10240B
#pragma unroll
        for (int j = 0; j < 3; j++) {
            int cb = 8 * j + c2l;
            if (cb <= 16) {
                int r0 = wbase + (lid >> 2);
                float bv0 = bos[cb];
                float bv1 = (cb + 1 < 17) ? bos[cb + 1] : 0.f;
                po[r0 * 20 + cb]           = acc[j][0] + bv0;
                po[r0 * 20 + cb + 1]       = acc[j][1] + bv1;
                po[(r0 + 8) * 20 + cb]     = acc[j][2] + bv0;
                po[(r0 + 8) * 20 + cb + 1] = acc[j][3] + bv1;
            }
        }
    }
    __syncthreads();

    // ---------------- per-sample tail (threads 0..127) ----------------
    if (tid < SS) {
        const int wray = tid >> 5;   // 0..3
        const float* myo = (const float*)(smem + AH) + tid * 20;
        const float sigma = fmaxf(myo[0], 0.f);
        const float* wrgb = (const float*)(smem + SM_WRGB);
        const float* brg  = (const float*)(smem + SM_BRGB);
        float rgbv[3];
#pragma unroll
        for (int cc = 0; cc < 3; cc++) {
            float r = brg[cc];
#pragma unroll
            for (int k = 0; k < 16; k++) r = fmaf(myo[1 + k], wrgb[k * 3 + cc], r);
            rgbv[cc] = __fdividef(1.0f, 1.0f + __expf(-r));
        }

        const float dtv   = g_dt;
        const float alpha = 1.0f - __expf(-sigma * dtv);
        const float q     = (1.0f - alpha) + 1e-10f;

        float p = q;
#pragma unroll
        for (int d = 1; d < 32; d <<= 1) {
            float u = __shfl_up_sync(0xffffffffu, p, d);
            if (lid >= d) p *= u;
        }
        __shared__ float wtot[4];
        if (lid == 31) wtot[wray] = p;
        BARSYNC(1, 128);
        float pre = 1.0f;
        for (int w = 0; w < wray; w++) pre *= wtot[w];
        float excl = __shfl_up_sync(0xffffffffu, p, 1);
        if (lid == 0) excl = 1.0f;
        const float T    = pre * excl;
        const float incl = pre * p;
        const float wgt  = (T > 1e-4f) ? (T * alpha) : 0.f;

        float v0 = wgt * rgbv[0], v1 = wgt * rgbv[1], v2 = wgt * rgbv[2];
#pragma unroll
        for (int off = 16; off > 0; off >>= 1) {
            v0 += __shfl_down_sync(0xffffffffu, v0, off);
            v1 += __shfl_down_sync(0xffffffffu, v1, off);
            v2 += __shfl_down_sync(0xffffffffu, v2, off);
        }
        __shared__ float redc[4][3];
        if (lid == 0) { redc[wray][0] = v0; redc[wray][1] = v1; redc[wray][2] = v2; }
        if (tid == SS - 1) out[3 * n + ray] = incl;
        BARSYNC(1, 128);
        if (tid == 0) {
            out[ray * 3 + 0] = redc[0][0] + redc[1][0] + redc[2][0] + redc[3][0];
            out[ray * 3 + 1] = redc[0][1] + redc[1][1] + redc[2][1] + redc[3][1];
            out[ray * 3 + 2] = redc[0][2] + redc[1][2] + redc[2][2] + redc[3][2];
        }
    }
}

extern "C" void kernel_launch(void* const* d_in, const int* in_sizes, int n_in,
                              void* d_out, int out_size) {
    const float* ox   = (const float*)d_in[0];
    const float* oy   = (const float*)d_in[1];
    const float* oz   = (const float*)d_in[2];
    const float* dxv  = (const float*)d_in[3];
    const float* dyv  = (const float*)d_in[4];
    const float* dzv  = (const float*)d_in[5];
    const float* tmin = (const float*)d_in[6];
    const float* tmax = (const float*)d_in[7];
    const float* W1   = (const float*)d_in[8];
    const float* b1   = (const float*)d_in[9];
    const float* W2   = (const float*)d_in[10];
    const float* b2   = (const float*)d_in[11];
    const float* Wo   = (const float*)d_in[12];
    const float* bo   = (const float*)d_in[13];
    const float* Wrgb = (const float*)d_in[14];
    const float* brgb = (const float*)d_in[15];
    float* out = (float*)d_out;
    const int n = in_sizes[0];

    cudaFuncSetAttribute(nerf_mma_kernel, cudaFuncAttributeMaxDynamicSharedMemorySize, SM_TOTAL);

    prep_kernel<<<1, 256>>>(tmin, tmax, W1, W2, Wo, n);
    nerf_mma_kernel<<<n, TPB, SM_TOTAL>>>(
        ox, oy, oz, dxv, dyv, dzv, tmin, tmax,
        b1, b2, bo, Wrgb, brgb, out, n);
}

// round 13
// speedup vs baseline: 3.5738x; 1.1642x over previous
#include <cuda_runtime.h>
#include <cuda_fp16.h>
#include <cstdint>
#include <math.h>

#define SS    128
#define LFREQ 10

__device__ float g_dt;
__device__ __align__(16) unsigned char g_wbuf[20480];   // pre-swizzled fp16 weights

#define GW_W1 0
#define GW_W2 8192
#define GW_WO 16384

// ---------------- helpers ----------------
__device__ __forceinline__ uint32_t smem_to_u32(const void* p) {
    uint32_t a;
    asm("{ .reg .u64 t; cvta.to.shared.u64 t, %1; cvt.u32.u64 %0, t; }" : "=r"(a) : "l"(p));
    return a;
}

__device__ __forceinline__ void ldsm4(uint32_t* r, uint32_t addr) {
    asm volatile("ldmatrix.sync.aligned.m8n8.x4.shared.b16 {%0,%1,%2,%3}, [%4];"
        : "=r"(r[0]), "=r"(r[1]), "=r"(r[2]), "=r"(r[3]) : "r"(addr));
}

__device__ __forceinline__ void mma16816(float* d, const uint32_t* a, uint32_t b0, uint32_t b1) {
    asm volatile("mma.sync.aligned.m16n8k16.row.col.f32.f16.f16.f32 "
        "{%0,%1,%2,%3}, {%4,%5,%6,%7}, {%8,%9}, {%0,%1,%2,%3};"
        : "+f"(d[0]), "+f"(d[1]), "+f"(d[2]), "+f"(d[3])
        : "r"(a[0]), "r"(a[1]), "r"(a[2]), "r"(a[3]), "r"(b0), "r"(b1));
}

__device__ __forceinline__ uint32_t pack2h(float a, float b) {
    __half2 hh = __floats2half2_rn(a, b);
    return *reinterpret_cast<uint32_t*>(&hh);
}

// swizzled tile byte offset: row-major, 128B rows, 16B granules XORed
__device__ __forceinline__ uint32_t sw_off(int row, int c4) {
    return (uint32_t)(row * 128 + ((c4 ^ (row & 7)) << 4));
}

// ---------------- SMEM layout (byte offsets) ----------------
#define SM_B1    0
#define SM_B2    256
#define SM_BO    512
#define SM_WRGB  640
#define SM_BRGB  832
#define SM_W     1024
#define SM_W1    (SM_W + GW_W1)
#define SM_W2    (SM_W + GW_W2)
#define SM_WO    (SM_W + GW_WO)
#define SM_A     21504   // 128 x 128B fp16 tile = 16384
#define SM_TOTAL (21504 + 16384)   // 37888

#define TPB 128

// -------- prep: dt reduction + weight conversion (one CTA) --------
__global__ void prep_kernel(const float* __restrict__ tmin, const float* __restrict__ tmax,
                            const float* __restrict__ W1, const float* __restrict__ W2,
                            const float* __restrict__ Wo, int n) {
    __shared__ float red[256];
    int tid = threadIdx.x;
    float acc = 0.f;
    for (int i = tid; i < n; i += 256) acc += tmax[i] - tmin[i];
    red[tid] = acc;
    __syncthreads();
    for (int s = 128; s > 0; s >>= 1) {
        if (tid < s) red[tid] += red[tid + s];
        __syncthreads();
    }
    if (tid == 0) g_dt = (red[0] / (float)n) / (float)SS;

    for (int idx = tid; idx < 64 * 64; idx += 256) {
        int nn = idx >> 6, k = idx & 63;
        float w = (k < 63) ? W1[k * 64 + nn] : 0.f;
        __half h = __float2half_rn(w);
        uint32_t off = sw_off(nn, k >> 3) + (k & 7) * 2;
        *(uint16_t*)(g_wbuf + GW_W1 + off) = *reinterpret_cast<uint16_t*>(&h);
    }
    for (int idx = tid; idx < 64 * 64; idx += 256) {
        int nn = idx >> 6, k = idx & 63;
        float w = W2[k * 64 + nn];
        __half h = __float2half_rn(w);
        uint32_t off = sw_off(nn, k >> 3) + (k & 7) * 2;
        *(uint16_t*)(g_wbuf + GW_W2 + off) = *reinterpret_cast<uint16_t*>(&h);
    }
    for (int idx = tid; idx < 32 * 64; idx += 256) {
        int nn = idx >> 6, k = idx & 63;
        float w = (nn < 17) ? Wo[k * 17 + nn] : 0.f;
        __half h = __float2half_rn(w);
        uint32_t off = sw_off(nn, k >> 3) + (k & 7) * 2;
        *(uint16_t*)(g_wbuf + GW_WO + off) = *reinterpret_cast<uint16_t*>(&h);
    }
}

__global__ void __launch_bounds__(TPB, 4)
nerf_mma_kernel(const float* __restrict__ ox, const float* __restrict__ oy,
                const float* __restrict__ oz, const float* __restrict__ dxv,
                const float* __restrict__ dyv, const float* __restrict__ dzv,
                const float* __restrict__ tmin, const float* __restrict__ tmax,
                const float* __restrict__ b1, const float* __restrict__ b2,
                const float* __restrict__ bo,
                const float* __restrict__ Wrgb, const float* __restrict__ brgb,
                float* __restrict__ out, int n)
{
    extern __shared__ __align__(1024) char smem[];
    const uint32_t sb = smem_to_u32(smem);
    const int tid  = threadIdx.x;
    const int lid  = tid & 31;
    const int wid  = tid >> 5;            // 0..3
    const int wbase = wid * 32;           // 32 rows per warp (2 m-tiles)
    const uint32_t AH = SM_A;
    const int ray = blockIdx.x;

    // ---- stage weights (vector copy of preconverted fp16 tiles) ----
    {
        const uint4* src = (const uint4*)g_wbuf;
        uint4* dst = (uint4*)(smem + SM_W);
        for (int i = tid; i < 1280; i += TPB) dst[i] = src[i];
        float* s = (float*)smem;
        for (int i = tid; i < 64; i += TPB) s[(SM_B1 >> 2) + i] = b1[i];
        for (int i = tid; i < 64; i += TPB) s[(SM_B2 >> 2) + i] = b2[i];
        for (int i = tid; i < 17; i += TPB) s[(SM_BO >> 2) + i] = bo[i];
        for (int i = tid; i < 48; i += TPB) s[(SM_WRGB >> 2) + i] = Wrgb[i];
        for (int i = tid; i < 3;  i += TPB) s[(SM_BRGB >> 2) + i] = brgb[i];
    }

    // ---- positional encodings -> A tile (row = sample = tid, fp16) ----
    {
        const float tmn = tmin[ray], tmx = tmax[ray];
        const float t  = fmaf((float)tid * (1.0f / (float)(SS - 1)), tmx - tmn, tmn);
        float e[64];
        e[0] = fmaf(dxv[ray], t, ox[ray]);
        e[1] = fmaf(dyv[ray], t, oy[ray]);
        e[2] = fmaf(dzv[ray], t, oz[ray]);
        e[63] = 0.f;
#pragma unroll 1
        for (int c = 0; c < 3; c++) {
            float sv, cv;
            __sincosf(e[c], &sv, &cv);
#pragma unroll
            for (int f = 0; f < LFREQ; f++) {
                e[3 + 20 * c + f]      = sv;
                e[3 + 20 * c + 10 + f] = cv;
                float ns = 2.0f * sv * cv;
                float nc = fmaf(cv, cv, -(sv * sv));
                sv = ns; cv = nc;
            }
        }
        uint32_t hi[32];
#pragma unroll
        for (int j = 0; j < 32; j++) hi[j] = pack2h(e[2 * j], e[2 * j + 1]);
#pragma unroll
        for (int q = 0; q < 8; q++) {
            uint32_t off = sw_off(tid, q);
            *(uint4*)(smem + AH + off) = make_uint4(hi[4*q], hi[4*q+1], hi[4*q+2], hi[4*q+3]);
        }
    }
    __syncthreads();

    // lane-derived ldmatrix coordinates
    const int lj = lid >> 3, lr = lid & 7;
    const int a_rl  = ((lj & 1) << 3) + lr;
    const int a_c4h = lj >> 1;
    const int b_nl  = ((lj >> 1) << 3) + lr;
    const int b_c4h = lj & 1;
    const int c2l   = 2 * (lid & 3);

    float acc[2][8][4];
    uint32_t ahr[2][4][4];   // register A fragments (fp16)

    // ================= layer 1 (A from smem, 2 m-tiles/warp) =================
#pragma unroll
    for (int mt = 0; mt < 2; mt++)
#pragma unroll
        for (int j = 0; j < 8; j++)
#pragma unroll
            for (int v = 0; v < 4; v++) acc[mt][j][v] = 0.f;

#pragma unroll
    for (int ks = 0; ks < 4; ks++) {
        uint32_t ahs[2][4];
#pragma unroll
        for (int mt = 0; mt < 2; mt++) {
            uint32_t off = sw_off(wbase + mt * 16 + a_rl, ks * 2 + a_c4h);
            ldsm4(ahs[mt], sb + AH + off);
        }
#pragma unroll
        for (int p = 0; p < 4; p++) {
            uint32_t wh[4];
            uint32_t off = sw_off(p * 16 + b_nl, ks * 2 + b_c4h);
            ldsm4(wh, sb + SM_W1 + off);
#pragma unroll
            for (int mt = 0; mt < 2; mt++) {
                mma16816(acc[mt][2*p],   ahs[mt], wh[0], wh[1]);
                mma16816(acc[mt][2*p+1], ahs[mt], wh[2], wh[3]);
            }
        }
    }

    // epilogue 1: bias+relu -> fp16 register A fragments
    {
        const float* bias = (const float*)(smem + SM_B1);
#pragma unroll
        for (int mt = 0; mt < 2; mt++)
#pragma unroll
            for (int j = 0; j < 8; j++) {
                int cb = 8 * j + c2l;
                float v0 = fmaxf(acc[mt][j][0] + bias[cb],     0.f);
                float v1 = fmaxf(acc[mt][j][1] + bias[cb + 1], 0.f);
                float v2 = fmaxf(acc[mt][j][2] + bias[cb],     0.f);
                float v3 = fmaxf(acc[mt][j][3] + bias[cb + 1], 0.f);
                int s = j >> 1, hf = j & 1;
                ahr[mt][s][2*hf]   = pack2h(v0, v1);
                ahr[mt][s][2*hf+1] = pack2h(v2, v3);
            }
    }

    // ================= layer 2 (A from registers) =================
#pragma unroll
    for (int mt = 0; mt < 2; mt++)
#pragma unroll
        for (int j = 0; j < 8; j++)
#pragma unroll
            for (int v = 0; v < 4; v++) acc[mt][j][v] = 0.f;

#pragma unroll
    for (int ks = 0; ks < 4; ks++) {
#pragma unroll
        for (int p = 0; p < 4; p++) {
            uint32_t wh[4];
            uint32_t off = sw_off(p * 16 + b_nl, ks * 2 + b_c4h);
            ldsm4(wh, sb + SM_W2 + off);
#pragma unroll
            for (int mt = 0; mt < 2; mt++) {
                mma16816(acc[mt][2*p],   ahr[mt][ks], wh[0], wh[1]);
                mma16816(acc[mt][2*p+1], ahr[mt][ks], wh[2], wh[3]);
            }
        }
    }

    // epilogue 2 -> overwrite register A fragments
    {
        const float* bias = (const float*)(smem + SM_B2);
#pragma unroll
        for (int mt = 0; mt < 2; mt++)
#pragma unroll
            for (int j = 0; j < 8; j++) {
                int cb = 8 * j + c2l;
                float v0 = fmaxf(acc[mt][j][0] + bias[cb],     0.f);
                float v1 = fmaxf(acc[mt][j][1] + bias[cb + 1], 0.f);
                float v2 = fmaxf(acc[mt][j][2] + bias[cb],     0.f);
                float v3 = fmaxf(acc[mt][j][3] + bias[cb + 1], 0.f);
                int s = j >> 1, hf = j & 1;
                ahr[mt][s][2*hf]   = pack2h(v0, v1);
                ahr[mt][s][2*hf+1] = pack2h(v2, v3);
            }
    }

    // ================= layer 3 (3 n-tiles: cols 0..23, 17 valid) =================
#pragma unroll
    for (int mt = 0; mt < 2; mt++)
#pragma unroll
        for (int j = 0; j < 3; j++)
#pragma unroll
            for (int v = 0; v < 4; v++) acc[mt][j][v] = 0.f;

#pragma unroll
    for (int ks = 0; ks < 4; ks++) {
#pragma unroll
        for (int p = 0; p < 2; p++) {
            uint32_t wh[4];
            uint32_t off = sw_off(p * 16 + b_nl, ks * 2 + b_c4h);
            ldsm4(wh, sb + SM_WO + off);
#pragma unroll
            for (int mt = 0; mt < 2; mt++) {
                mma16816(acc[mt][2*p], ahr[mt][ks], wh[0], wh[1]);
                if (p == 0)
                    mma16816(acc[mt][1], ahr[mt][ks], wh[2], wh[3]);
            }
        }
    }

    // A tile dead (layers 2-3 ran from registers); alias OUT staging onto A.
    // Warp w owns rows [32w,32w+32): both A reads and OUT rows are warp-private.
    __syncthreads();
    {
        const float* bos = (const float*)(smem + SM_BO);
        float* po = (float*)(smem + AH);   // 128 rows x 20 f32 = 10240B
#pragma unroll
        for (int mt = 0; mt < 2; mt++)
#pragma unroll
            for (int j = 0; j < 3; j++) {
                int cb = 8 * j + c2l;
                if (cb <= 16) {
                    int r0 = wbase + mt * 16 + (lid >> 2);
                    float bv0 = bos[cb];
                    float bv1 = (cb + 1 < 17) ? bos[cb + 1] : 0.f;
                    po[r0 * 20 + cb]           = acc[mt][j][0] + bv0;
                    po[r0 * 20 + cb + 1]       = acc[mt][j][1] + bv1;
                    po[(r0 + 8) * 20 + cb]     = acc[mt][j][2] + bv0;
                    po[(r0 + 8) * 20 + cb + 1] = acc[mt][j][3] + bv1;
                }
            }
    }
    __syncthreads();

    // ---------------- per-sample tail (all 128 threads) ----------------
    {
        const float* myo = (const float*)(smem + AH) + tid * 20;
        const float sigma = fmaxf(myo[0], 0.f);
        const float* wrgb = (const float*)(smem + SM_WRGB);
        const float* brg  = (const float*)(smem + SM_BRGB);
        float rgbv[3];
#pragma unroll
        for (int cc = 0; cc < 3; cc++) {
            float r = brg[cc];
#pragma unroll
            for (int k = 0; k < 16; k++) r = fmaf(myo[1 + k], wrgb[k * 3 + cc], r);
            rgbv[cc] = __fdividef(1.0f, 1.0f + __expf(-r));
        }

        const float dtv   = g_dt;
        const float alpha = 1.0f - __expf(-sigma * dtv);
        const float q     = (1.0f - alpha) + 1e-10f;

        float p = q;
#pragma unroll
        for (int d = 1; d < 32; d <<= 1) {
            float u = __shfl_up_sync(0xffffffffu, p, d);
            if (lid >= d) p *= u;
        }
        __shared__ float wtot[4];
        if (lid == 31) wtot[wid] = p;
        __syncthreads();
        float pre = 1.0f;
        for (int w = 0; w < wid; w++) pre *= wtot[w];
        float excl = __shfl_up_sync(0xffffffffu, p, 1);
        if (lid == 0) excl = 1.0f;
        const float T    = pre * excl;
        const float incl = pre * p;
        const float wgt  = (T > 1e-4f) ? (T * alpha) : 0.f;

        float v0 = wgt * rgbv[0], v1 = wgt * rgbv[1], v2 = wgt * rgbv[2];
#pragma unroll
        for (int off = 16; off > 0; off >>= 1) {
            v0 += __shfl_down_sync(0xffffffffu, v0, off);
            v1 += __shfl_down_sync(0xffffffffu, v1, off);
            v2 += __shfl_down_sync(0xffffffffu, v2, off);
        }
        __shared__ float redc[4][3];
        if (lid == 0) { redc[wid][0] = v0; redc[wid][1] = v1; redc[wid][2] = v2; }
        if (tid == SS - 1) out[3 * n + ray] = incl;
        __syncthreads();
        if (tid == 0) {
            out[ray * 3 + 0] = redc[0][0] + redc[1][0] + redc[2][0] + redc[3][0];
            out[ray * 3 + 1] = redc[0][1] + redc[1][1] + redc[2][1] + redc[3][1];
            out[ray * 3 + 2] = redc[0][2] + redc[1][2] + redc[2][2] + redc[3][2];
        }
    }
}

extern "C" void kernel_launch(void* const* d_in, const int* in_sizes, int n_in,
                              void* d_out, int out_size) {
    const float* ox   = (const float*)d_in[0];
    const float* oy   = (const float*)d_in[1];
    const float* oz   = (const float*)d_in[2];
    const float* dxv  = (const float*)d_in[3];
    const float* dyv  = (const float*)d_in[4];
    const float* dzv  = (const float*)d_in[5];
    const float* tmin = (const float*)d_in[6];
    const float* tmax = (const float*)d_in[7];
    const float* W1   = (const float*)d_in[8];
    const float* b1   = (const float*)d_in[9];
    const float* W2   = (const float*)d_in[10];
    const float* b2   = (const float*)d_in[11];
    const float* Wo   = (const float*)d_in[12];
    const float* bo   = (const float*)d_in[13];
    const float* Wrgb = (const float*)d_in[14];
    const float* brgb = (const float*)d_in[15];
    float* out = (float*)d_out;
    const int n = in_sizes[0];

    cudaFuncSetAttribute(nerf_mma_kernel, cudaFuncAttributeMaxDynamicSharedMemorySize, SM_TOTAL);

    prep_kernel<<<1, 256>>>(tmin, tmax, W1, W2, Wo, n);
    nerf_mma_kernel<<<n, TPB, SM_TOTAL>>>(
        ox, oy, oz, dxv, dyv, dzv, tmin, tmax,
        b1, b2, bo, Wrgb, brgb, out, n);
}

// round 14
// speedup vs baseline: 3.8545x; 1.0785x over previous
#include <cuda_runtime.h>
#include <cuda_fp16.h>
#include <cstdint>
#include <math.h>

#define SS    128
#define LFREQ 10

__device__ float g_dt;
__device__ __align__(16) unsigned char g_wbuf[20480];   // pre-swizzled fp16 weights

#define GW_W1 0
#define GW_W2 8192
#define GW_WO 16384

// ---------------- helpers ----------------
__device__ __forceinline__ uint32_t smem_to_u32(const void* p) {
    uint32_t a;
    asm("{ .reg .u64 t; cvta.to.shared.u64 t, %1; cvt.u32.u64 %0, t; }" : "=r"(a) : "l"(p));
    return a;
}

__device__ __forceinline__ void ldsm4(uint32_t* r, uint32_t addr) {
    asm volatile("ldmatrix.sync.aligned.m8n8.x4.shared.b16 {%0,%1,%2,%3}, [%4];"
        : "=r"(r[0]), "=r"(r[1]), "=r"(r[2]), "=r"(r[3]) : "r"(addr));
}

__device__ __forceinline__ void mma16816(float* d, const uint32_t* a, uint32_t b0, uint32_t b1) {
    asm volatile("mma.sync.aligned.m16n8k16.row.col.f32.f16.f16.f32 "
        "{%0,%1,%2,%3}, {%4,%5,%6,%7}, {%8,%9}, {%0,%1,%2,%3};"
        : "+f"(d[0]), "+f"(d[1]), "+f"(d[2]), "+f"(d[3])
        : "r"(a[0]), "r"(a[1]), "r"(a[2]), "r"(a[3]), "r"(b0), "r"(b1));
}

__device__ __forceinline__ uint32_t pack2h(float a, float b) {
    __half2 hh = __floats2half2_rn(a, b);
    return *reinterpret_cast<uint32_t*>(&hh);
}

// swizzled tile byte offset: row-major, 128B rows, 16B granules XORed
__device__ __forceinline__ uint32_t sw_off(int row, int c4) {
    return (uint32_t)(row * 128 + ((c4 ^ (row & 7)) << 4));
}

// ---------------- SMEM layout (byte offsets) ----------------
#define SM_B1    0
#define SM_B2    256
#define SM_BO    512
#define SM_WRGB  640
#define SM_BRGB  832
#define SM_W     1024
#define SM_W1    (SM_W + GW_W1)
#define SM_W2    (SM_W + GW_W2)
#define SM_WO    (SM_W + GW_WO)
#define SM_A     21504   // 128 x 128B fp16 tile = 16384
#define SM_TOTAL (21504 + 16384)   // 37888

#define OSTRIDE 21       // OUT staging stride in floats (coprime with 32 banks)
#define TPB 128

// -------- prep: dt reduction + weight conversion (one CTA) --------
__global__ void prep_kernel(const float* __restrict__ tmin, const float* __restrict__ tmax,
                            const float* __restrict__ W1, const float* __restrict__ W2,
                            const float* __restrict__ Wo, int n) {
    __shared__ float red[256];
    int tid = threadIdx.x;
    float acc = 0.f;
    for (int i = tid; i < n; i += 256) acc += tmax[i] - tmin[i];
    red[tid] = acc;
    __syncthreads();
    for (int s = 128; s > 0; s >>= 1) {
        if (tid < s) red[tid] += red[tid + s];
        __syncthreads();
    }
    if (tid == 0) g_dt = (red[0] / (float)n) / (float)SS;

    for (int idx = tid; idx < 64 * 64; idx += 256) {
        int nn = idx >> 6, k = idx & 63;
        float w = (k < 63) ? W1[k * 64 + nn] : 0.f;
        __half h = __float2half_rn(w);
        uint32_t off = sw_off(nn, k >> 3) + (k & 7) * 2;
        *(uint16_t*)(g_wbuf + GW_W1 + off) = *reinterpret_cast<uint16_t*>(&h);
    }
    for (int idx = tid; idx < 64 * 64; idx += 256) {
        int nn = idx >> 6, k = idx & 63;
        float w = W2[k * 64 + nn];
        __half h = __float2half_rn(w);
        uint32_t off = sw_off(nn, k >> 3) + (k & 7) * 2;
        *(uint16_t*)(g_wbuf + GW_W2 + off) = *reinterpret_cast<uint16_t*>(&h);
    }
    for (int idx = tid; idx < 32 * 64; idx += 256) {
        int nn = idx >> 6, k = idx & 63;
        float w = (nn < 17) ? Wo[k * 17 + nn] : 0.f;
        __half h = __float2half_rn(w);
        uint32_t off = sw_off(nn, k >> 3) + (k & 7) * 2;
        *(uint16_t*)(g_wbuf + GW_WO + off) = *reinterpret_cast<uint16_t*>(&h);
    }
}

__global__ void __launch_bounds__(TPB, 5)
nerf_mma_kernel(const float* __restrict__ ox, const float* __restrict__ oy,
                const float* __restrict__ oz, const float* __restrict__ dxv,
                const float* __restrict__ dyv, const float* __restrict__ dzv,
                const float* __restrict__ tmin, const float* __restrict__ tmax,
                const float* __restrict__ b1, const float* __restrict__ b2,
                const float* __restrict__ bo,
                const float* __restrict__ Wrgb, const float* __restrict__ brgb,
                float* __restrict__ out, int n)
{
    extern __shared__ __align__(1024) char smem[];
    const uint32_t sb = smem_to_u32(smem);
    const int tid  = threadIdx.x;
    const int lid  = tid & 31;
    const int wid  = tid >> 5;            // 0..3
    const int wbase = wid * 32;           // 32 rows per warp (2 m-tiles)
    const uint32_t AH = SM_A;
    const int ray = blockIdx.x;

    // ---- stage weights (vector copy of preconverted fp16 tiles) ----
    {
        const uint4* src = (const uint4*)g_wbuf;
        uint4* dst = (uint4*)(smem + SM_W);
        for (int i = tid; i < 1280; i += TPB) dst[i] = src[i];
        float* s = (float*)smem;
        for (int i = tid; i < 64; i += TPB) s[(SM_B1 >> 2) + i] = b1[i];
        for (int i = tid; i < 64; i += TPB) s[(SM_B2 >> 2) + i] = b2[i];
        for (int i = tid; i < 17; i += TPB) s[(SM_BO >> 2) + i] = bo[i];
        for (int i = tid; i < 48; i += TPB) s[(SM_WRGB >> 2) + i] = Wrgb[i];
        for (int i = tid; i < 3;  i += TPB) s[(SM_BRGB >> 2) + i] = brgb[i];
    }

    // ---- positional encodings -> A tile (row = sample = tid, fp16) ----
    {
        const float tmn = tmin[ray], tmx = tmax[ray];
        const float t  = fmaf((float)tid * (1.0f / (float)(SS - 1)), tmx - tmn, tmn);
        float e[64];
        e[0] = fmaf(dxv[ray], t, ox[ray]);
        e[1] = fmaf(dyv[ray], t, oy[ray]);
        e[2] = fmaf(dzv[ray], t, oz[ray]);
        e[63] = 0.f;
#pragma unroll 1
        for (int c = 0; c < 3; c++) {
            float sv, cv;
            __sincosf(e[c], &sv, &cv);
#pragma unroll
            for (int f = 0; f < LFREQ; f++) {
                e[3 + 20 * c + f]      = sv;
                e[3 + 20 * c + 10 + f] = cv;
                float ns = 2.0f * sv * cv;
                float nc = fmaf(cv, cv, -(sv * sv));
                sv = ns; cv = nc;
            }
        }
#pragma unroll
        for (int q = 0; q < 8; q++) {
            uint32_t off = sw_off(tid, q);
            *(uint4*)(smem + AH + off) = make_uint4(
                pack2h(e[8*q + 0], e[8*q + 1]), pack2h(e[8*q + 2], e[8*q + 3]),
                pack2h(e[8*q + 4], e[8*q + 5]), pack2h(e[8*q + 6], e[8*q + 7]));
        }
    }
    __syncthreads();

    // lane-derived ldmatrix coordinates
    const int lj = lid >> 3, lr = lid & 7;
    const int a_rl  = ((lj & 1) << 3) + lr;
    const int a_c4h = lj >> 1;
    const int b_nl  = ((lj >> 1) << 3) + lr;
    const int b_c4h = lj & 1;
    const int c2l   = 2 * (lid & 3);

    uint32_t ahr[2][4][4];   // register A fragments for layer 2 (fp16)

    // ================= layer 1 (A from smem, n-halves) =================
#pragma unroll
    for (int h = 0; h < 2; h++) {
        float acc[2][4][4];
#pragma unroll
        for (int mt = 0; mt < 2; mt++)
#pragma unroll
            for (int j = 0; j < 4; j++)
#pragma unroll
                for (int v = 0; v < 4; v++) acc[mt][j][v] = 0.f;

#pragma unroll
        for (int ks = 0; ks < 4; ks++) {
            uint32_t ahs[2][4];
#pragma unroll
            for (int mt = 0; mt < 2; mt++) {
                uint32_t off = sw_off(wbase + mt * 16 + a_rl, ks * 2 + a_c4h);
                ldsm4(ahs[mt], sb + AH + off);
            }
#pragma unroll
            for (int pp = 0; pp < 2; pp++) {
                int p = 2 * h + pp;
                uint32_t wh[4];
                uint32_t off = sw_off(p * 16 + b_nl, ks * 2 + b_c4h);
                ldsm4(wh, sb + SM_W1 + off);
#pragma unroll
                for (int mt = 0; mt < 2; mt++) {
                    mma16816(acc[mt][2*pp],   ahs[mt], wh[0], wh[1]);
                    mma16816(acc[mt][2*pp+1], ahs[mt], wh[2], wh[3]);
                }
            }
        }
        // epilogue: bias+relu -> ahr (cols 32h..32h+31)
        const float* bias = (const float*)(smem + SM_B1);
#pragma unroll
        for (int mt = 0; mt < 2; mt++)
#pragma unroll
            for (int jj = 0; jj < 4; jj++) {
                int jg = 4 * h + jj;
                int cb = 8 * jg + c2l;
                float v0 = fmaxf(acc[mt][jj][0] + bias[cb],     0.f);
                float v1 = fmaxf(acc[mt][jj][1] + bias[cb + 1], 0.f);
                float v2 = fmaxf(acc[mt][jj][2] + bias[cb],     0.f);
                float v3 = fmaxf(acc[mt][jj][3] + bias[cb + 1], 0.f);
                int s = jg >> 1, hf = jg & 1;
                ahr[mt][s][2*hf]   = pack2h(v0, v1);
                ahr[mt][s][2*hf+1] = pack2h(v2, v3);
            }
    }

    // ================= layer 2 (A from registers, n-halves, out -> smem A) ===
    __syncwarp();   // A tile consumed by this warp's layer-1 ldsm; safe to overwrite own rows
#pragma unroll
    for (int h = 0; h < 2; h++) {
        float acc[2][4][4];
#pragma unroll
        for (int mt = 0; mt < 2; mt++)
#pragma unroll
            for (int j = 0; j < 4; j++)
#pragma unroll
                for (int v = 0; v < 4; v++) acc[mt][j][v] = 0.f;

#pragma unroll
        for (int ks = 0; ks < 4; ks++) {
#pragma unroll
            for (int pp = 0; pp < 2; pp++) {
                int p = 2 * h + pp;
                uint32_t wh[4];
                uint32_t off = sw_off(p * 16 + b_nl, ks * 2 + b_c4h);
                ldsm4(wh, sb + SM_W2 + off);
#pragma unroll
                for (int mt = 0; mt < 2; mt++) {
                    mma16816(acc[mt][2*pp],   ahr[mt][ks], wh[0], wh[1]);
                    mma16816(acc[mt][2*pp+1], ahr[mt][ks], wh[2], wh[3]);
                }
            }
        }
        // epilogue: bias+relu -> packed fp16 back into smem A (warp-private rows)
        const float* bias = (const float*)(smem + SM_B2);
#pragma unroll
        for (int mt = 0; mt < 2; mt++)
#pragma unroll
            for (int jj = 0; jj < 4; jj++) {
                int jg = 4 * h + jj;
                int cb = 8 * jg + c2l;
                float v0 = fmaxf(acc[mt][jj][0] + bias[cb],     0.f);
                float v1 = fmaxf(acc[mt][jj][1] + bias[cb + 1], 0.f);
                float v2 = fmaxf(acc[mt][jj][2] + bias[cb],     0.f);
                float v3 = fmaxf(acc[mt][jj][3] + bias[cb + 1], 0.f);
                int r0 = wbase + mt * 16 + (lid >> 2);
                uint32_t o0 = sw_off(r0,     cb >> 3) + (cb & 7) * 2;
                uint32_t o1 = sw_off(r0 + 8, cb >> 3) + (cb & 7) * 2;
                *(uint32_t*)(smem + AH + o0) = pack2h(v0, v1);
                *(uint32_t*)(smem + AH + o1) = pack2h(v2, v3);
            }
    }
    __syncwarp();

    // ================= layer 3 (A from smem, 3 n-tiles: 17 valid) =============
    float acc3[2][3][4];
#pragma unroll
    for (int mt = 0; mt < 2; mt++)
#pragma unroll
        for (int j = 0; j < 3; j++)
#pragma unroll
            for (int v = 0; v < 4; v++) acc3[mt][j][v] = 0.f;

#pragma unroll
    for (int ks = 0; ks < 4; ks++) {
        uint32_t ahs[2][4];
#pragma unroll
        for (int mt = 0; mt < 2; mt++) {
            uint32_t off = sw_off(wbase + mt * 16 + a_rl, ks * 2 + a_c4h);
            ldsm4(ahs[mt], sb + AH + off);
        }
#pragma unroll
        for (int p = 0; p < 2; p++) {
            uint32_t wh[4];
            uint32_t off = sw_off(p * 16 + b_nl, ks * 2 + b_c4h);
            ldsm4(wh, sb + SM_WO + off);
#pragma unroll
            for (int mt = 0; mt < 2; mt++) {
                mma16816(acc3[mt][2*p], ahs[mt], wh[0], wh[1]);
                if (p == 0)
                    mma16816(acc3[mt][1], ahs[mt], wh[2], wh[3]);
            }
        }
    }

    // A tile dead; alias OUT staging onto it (stride 21 -> conflict-free tail)
    __syncthreads();
    {
        const float* bos = (const float*)(smem + SM_BO);
        float* po = (float*)(smem + AH);   // 128 rows x 21 f32 = 10752B
#pragma unroll
        for (int mt = 0; mt < 2; mt++)
#pragma unroll
            for (int j = 0; j < 3; j++) {
                int cb = 8 * j + c2l;
                if (cb <= 16) {
                    int r0 = wbase + mt * 16 + (lid >> 2);
                    float bv0 = bos[cb];
                    float bv1 = (cb + 1 < 17) ? bos[cb + 1] : 0.f;
                    po[r0 * OSTRIDE + cb]           = acc3[mt][j][0] + bv0;
                    po[r0 * OSTRIDE + cb + 1]       = acc3[mt][j][1] + bv1;
                    po[(r0 + 8) * OSTRIDE + cb]     = acc3[mt][j][2] + bv0;
                    po[(r0 + 8) * OSTRIDE + cb + 1] = acc3[mt][j][3] + bv1;
                }
            }
    }
    __syncthreads();

    // ---------------- per-sample tail (all 128 threads) ----------------
    {
        const float* myo = (const float*)(smem + AH) + tid * OSTRIDE;
        const float sigma = fmaxf(myo[0], 0.f);
        const float* wrgb = (const float*)(smem + SM_WRGB);
        const float* brg  = (const float*)(smem + SM_BRGB);
        float rgbv[3];
#pragma unroll
        for (int cc = 0; cc < 3; cc++) {
            float r = brg[cc];
#pragma unroll
            for (int k = 0; k < 16; k++) r = fmaf(myo[1 + k], wrgb[k * 3 + cc], r);
            rgbv[cc] = __fdividef(1.0f, 1.0f + __expf(-r));
        }

        const float dtv   = g_dt;
        const float alpha = 1.0f - __expf(-sigma * dtv);
        const float q     = (1.0f - alpha) + 1e-10f;

        float p = q;
#pragma unroll
        for (int d = 1; d < 32; d <<= 1) {
            float u = __shfl_up_sync(0xffffffffu, p, d);
            if (lid >= d) p *= u;
        }
        __shared__ float wtot[4];
        if (lid == 31) wtot[wid] = p;
        __syncthreads();
        float pre = 1.0f;
        for (int w = 0; w < wid; w++) pre *= wtot[w];
        float excl = __shfl_up_sync(0xffffffffu, p, 1);
        if (lid == 0) excl = 1.0f;
        const float T    = pre * excl;
        const float incl = pre * p;
        const float wgt  = (T > 1e-4f) ? (T * alpha) : 0.f;

        float v0 = wgt * rgbv[0], v1 = wgt * rgbv[1], v2 = wgt * rgbv[2];
#pragma unroll
        for (int off = 16; off > 0; off >>= 1) {
            v0 += __shfl_down_sync(0xffffffffu, v0, off);
            v1 += __shfl_down_sync(0xffffffffu, v1, off);
            v2 += __shfl_down_sync(0xffffffffu, v2, off);
        }
        __shared__ float redc[4][3];
        if (lid == 0) { redc[wid][0] = v0; redc[wid][1] = v1; redc[wid][2] = v2; }
        if (tid == SS - 1) out[3 * n + ray] = incl;
        __syncthreads();
        if (tid == 0) {
            out[ray * 3 + 0] = redc[0][0] + redc[1][0] + redc[2][0] + redc[3][0];
            out[ray * 3 + 1] = redc[0][1] + redc[1][1] + redc[2][1] + redc[3][1];
            out[ray * 3 + 2] = redc[0][2] + redc[1][2] + redc[2][2] + redc[3][2];
        }
    }
}

extern "C" void kernel_launch(void* const* d_in, const int* in_sizes, int n_in,
                              void* d_out, int out_size) {
    const float* ox   = (const float*)d_in[0];
    const float* oy   = (const float*)d_in[1];
    const float* oz   = (const float*)d_in[2];
    const float* dxv  = (const float*)d_in[3];
    const float* dyv  = (const float*)d_in[4];
    const float* dzv  = (const float*)d_in[5];
    const float* tmin = (const float*)d_in[6];
    const float* tmax = (const float*)d_in[7];
    const float* W1   = (const float*)d_in[8];
    const float* b1   = (const float*)d_in[9];
    const float* W2   = (const float*)d_in[10];
    const float* b2   = (const float*)d_in[11];
    const float* Wo   = (const float*)d_in[12];
    const float* bo   = (const float*)d_in[13];
    const float* Wrgb = (const float*)d_in[14];
    const float* brgb = (const float*)d_in[15];
    float* out = (float*)d_out;
    const int n = in_sizes[0];

    cudaFuncSetAttribute(nerf_mma_kernel, cudaFuncAttributeMaxDynamicSharedMemorySize, SM_TOTAL);

    prep_kernel<<<1, 256>>>(tmin, tmax, W1, W2, Wo, n);
    nerf_mma_kernel<<<n, TPB, SM_TOTAL>>>(
        ox, oy, oz, dxv, dyv, dzv, tmin, tmax,
        b1, b2, bo, Wrgb, brgb, out, n);
}